// round 1
// baseline (speedup 1.0000x reference)
#include <cuda_runtime.h>
#include <math.h>

// ---------------------------------------------------------------------------
// TaskAwareMoE: top-2 sparse reformulation of the dense reference.
//   out[t] = sum_{k=0,1} p_k * FFN_{e_k}(x[t]) + (1-p_0) * FFN_u(x[t])
//   logits written to d_out tail.
// ---------------------------------------------------------------------------

#define D_MODEL   512
#define D_FF      2048
#define N_EXPERTS 8
#define BATCH     8
#define SEQ       1024
#define TOK       (BATCH * SEQ)            // 8192
#define EXP_ROWS  (2 * TOK)                // 16384 expert assignments
#define TOT_ROWS  (EXP_ROWS + TOK)         // 24576 incl. universal
#define OUT_ELEMS (TOK * D_MODEL)          // 4,194,304

// ----------------------------- static scratch ------------------------------
__device__ float g_H[(size_t)TOT_ROWS * D_FF];   // 201 MB, hidden activations
__device__ int   g_count[N_EXPERTS + 1];
__device__ int   g_offset[N_EXPERTS + 2];
__device__ int   g_tok_e0[TOK];
__device__ int   g_tok_e1[TOK];
__device__ float g_tok_p0[TOK];
__device__ float g_tok_p1[TOK];
__device__ float g_tok_om[TOK];
__device__ int   g_assign_tok[TOT_ROWS];
__device__ float g_assign_w[TOT_ROWS];

// ----------------------------- zero / init ---------------------------------
__global__ void k_zero(float4* __restrict__ out4) {
    unsigned i = blockIdx.x * 256u + threadIdx.x;
    if (i < OUT_ELEMS / 4) out4[i] = make_float4(0.f, 0.f, 0.f, 0.f);
    if (blockIdx.x == 0 && threadIdx.x <= N_EXPERTS) g_count[threadIdx.x] = 0;
}

// ----------------------------- gating --------------------------------------
// One block per token. logits[e] = [x, task_vec] @ gate_w + gate_b
__global__ void k_gate(const float* __restrict__ x,
                       const int*   __restrict__ task_ids,
                       const float* __restrict__ temb,
                       const float* __restrict__ gw,
                       const float* __restrict__ gb,
                       float* __restrict__ out_logits) {
    const int t   = blockIdx.x;
    const int tid = threadIdx.x;
    const int b   = t / SEQ;
    const int task = task_ids[b];
    const float* xr = x    + (size_t)t    * D_MODEL;
    const float* tr = temb + (size_t)task * D_MODEL;

    float acc[N_EXPERTS];
#pragma unroll
    for (int e = 0; e < N_EXPERTS; e++) acc[e] = 0.f;

    for (int d = tid; d < 2 * D_MODEL; d += 256) {
        float v = (d < D_MODEL) ? xr[d] : tr[d - D_MODEL];
        const float* g = gw + (size_t)d * N_EXPERTS;
#pragma unroll
        for (int e = 0; e < N_EXPERTS; e++) acc[e] += v * g[e];
    }

    // warp reduce then cross-warp via smem
#pragma unroll
    for (int e = 0; e < N_EXPERTS; e++)
#pragma unroll
        for (int off = 16; off > 0; off >>= 1)
            acc[e] += __shfl_down_sync(0xffffffffu, acc[e], off);

    __shared__ float s_acc[8][N_EXPERTS];
    const int warp = tid >> 5, lane = tid & 31;
    if (lane == 0) {
#pragma unroll
        for (int e = 0; e < N_EXPERTS; e++) s_acc[warp][e] = acc[e];
    }
    __syncthreads();

    if (tid == 0) {
        float lg[N_EXPERTS];
#pragma unroll
        for (int e = 0; e < N_EXPERTS; e++) {
            float s = gb[e];
#pragma unroll
            for (int w = 0; w < 8; w++) s += s_acc[w][e];
            lg[e] = s;
            out_logits[(size_t)t * N_EXPERTS + e] = s;
        }
        // top-2 (ties -> lowest index, matches lax.top_k)
        int e0 = 0; float v0 = lg[0];
#pragma unroll
        for (int e = 1; e < N_EXPERTS; e++) if (lg[e] > v0) { v0 = lg[e]; e0 = e; }
        int e1 = -1; float v1 = -1e30f;
#pragma unroll
        for (int e = 0; e < N_EXPERTS; e++)
            if (e != e0 && lg[e] > v1) { v1 = lg[e]; e1 = e; }

        float ex = expf(v1 - v0);          // <= 1
        float p0 = 1.f / (1.f + ex);
        float p1 = ex / (1.f + ex);
        g_tok_e0[t] = e0;  g_tok_e1[t] = e1;
        g_tok_p0[t] = p0;  g_tok_p1[t] = p1;
        g_tok_om[t] = 1.f - p0;            // omega = 1 - max(gates)
        atomicAdd(&g_count[e0], 1);
        atomicAdd(&g_count[e1], 1);
    }
}

// ----------------------------- offsets -------------------------------------
__global__ void k_scan() {
    if (blockIdx.x == 0 && threadIdx.x == 0) {
        int o = 0;
        for (int e = 0; e < N_EXPERTS; e++) { g_offset[e] = o; o += g_count[e]; }
        g_offset[N_EXPERTS]     = o;          // == EXP_ROWS
        g_offset[N_EXPERTS + 1] = o + TOK;
    }
}

// ----------------------------- build routing lists -------------------------
// Deterministic per-expert token lists via block-wide scan. Block 8 = universal.
__global__ void k_build() {
    const int e   = blockIdx.x;
    const int tid = threadIdx.x;

    if (e == N_EXPERTS) {  // universal expert: identity list, weight omega
        const int base = g_offset[N_EXPERTS];
        for (int t = tid; t < TOK; t += 256) {
            g_assign_tok[base + t] = t;
            g_assign_w[base + t]   = g_tok_om[t];
        }
        return;
    }

    __shared__ int s_scan[256];
    __shared__ int s_base;
    if (tid == 0) s_base = g_offset[e];
    __syncthreads();

    for (int t0 = 0; t0 < TOK; t0 += 256) {
        const int t = t0 + tid;
        int flag = 0; float w = 0.f;
        if (g_tok_e0[t] == e)      { flag = 1; w = g_tok_p0[t]; }
        else if (g_tok_e1[t] == e) { flag = 1; w = g_tok_p1[t]; }

        s_scan[tid] = flag;
        __syncthreads();
        for (int off = 1; off < 256; off <<= 1) {
            int v = (tid >= off) ? s_scan[tid - off] : 0;
            __syncthreads();
            s_scan[tid] += v;
            __syncthreads();
        }
        const int incl  = s_scan[tid];
        const int total = s_scan[255];
        const int base  = s_base;
        __syncthreads();
        if (flag) {
            const int pos = base + incl - 1;
            g_assign_tok[pos] = t;
            g_assign_w[pos]   = w;
        }
        if (tid == 0) s_base = base + total;
        __syncthreads();
    }
}

// ----------------------------- FFN stage 1: H = gelu(X @ W1 + b1) ----------
// 128x128 tile, 8x8 microtile, BK=16. grid (F/128, ceil(8192/128), 9)
__global__ void __launch_bounds__(256, 2)
k_ffn1(const float* __restrict__ x,
       const float* __restrict__ w1,  const float* __restrict__ b1,
       const float* __restrict__ uw1, const float* __restrict__ ub1) {
    const int z    = blockIdx.z;
    const int roff = g_offset[z];
    const int cnt  = g_offset[z + 1] - roff;
    const int m0   = blockIdx.y * 128;
    if (m0 >= cnt) return;
    const int f0   = blockIdx.x * 128;

    const float* __restrict__ W    = (z < N_EXPERTS)
        ? (w1 + (size_t)z * D_MODEL * D_FF) : uw1;
    const float* __restrict__ bias = (z < N_EXPERTS) ? (b1 + (size_t)z * D_FF) : ub1;

    __shared__ int   s_tok[128];
    __shared__ float As[128][16];
    __shared__ float Bs[16][128];

    const int tid = threadIdx.x;
    const int tx  = tid & 15;
    const int ty  = tid >> 4;

    if (tid < 128) {
        const int mm = m0 + tid;
        s_tok[tid] = g_assign_tok[roff + ((mm < cnt) ? mm : 0)];
    }
    __syncthreads();

    float acc[8][8];
#pragma unroll
    for (int i = 0; i < 8; i++)
#pragma unroll
        for (int j = 0; j < 8; j++) acc[i][j] = 0.f;

    for (int k0 = 0; k0 < D_MODEL; k0 += 16) {
#pragma unroll
        for (int q = 0; q < 8; q++) {
            const int e = tid + q * 256;
            const int m = e >> 4, kk = e & 15;
            As[m][kk] = x[(size_t)s_tok[m] * D_MODEL + k0 + kk];
        }
#pragma unroll
        for (int q = 0; q < 8; q++) {
            const int e = tid + q * 256;
            const int kk = e >> 7, f = e & 127;
            Bs[kk][f] = W[(size_t)(k0 + kk) * D_FF + f0 + f];
        }
        __syncthreads();
#pragma unroll
        for (int kk = 0; kk < 16; kk++) {
            float a[8], b[8];
#pragma unroll
            for (int i = 0; i < 8; i++) a[i] = As[ty + 16 * i][kk];
#pragma unroll
            for (int j = 0; j < 8; j++) b[j] = Bs[kk][tx + 16 * j];
#pragma unroll
            for (int i = 0; i < 8; i++)
#pragma unroll
                for (int j = 0; j < 8; j++)
                    acc[i][j] = fmaf(a[i], b[j], acc[i][j]);
        }
        __syncthreads();
    }

#pragma unroll
    for (int i = 0; i < 8; i++) {
        const int m = ty + 16 * i;
        if (m0 + m < cnt) {
            const size_t r = (size_t)(roff + m0 + m);
#pragma unroll
            for (int j = 0; j < 8; j++) {
                const int f = f0 + tx + 16 * j;
                float h = acc[i][j] + bias[f];
                h = 0.5f * h * (1.0f + erff(h * 0.70710678118654752f)); // exact gelu
                g_H[r * D_FF + f] = h;
            }
        }
    }
}

// ----------------------------- FFN stage 2: out += w * (H @ W2 + b2) -------
// grid (D/128, ceil(8192/128), 9)
__global__ void __launch_bounds__(256, 2)
k_ffn2(float* __restrict__ out,
       const float* __restrict__ w2,  const float* __restrict__ b2,
       const float* __restrict__ uw2, const float* __restrict__ ub2) {
    const int z    = blockIdx.z;
    const int roff = g_offset[z];
    const int cnt  = g_offset[z + 1] - roff;
    const int m0   = blockIdx.y * 128;
    if (m0 >= cnt) return;
    const int d0   = blockIdx.x * 128;

    const float* __restrict__ W    = (z < N_EXPERTS)
        ? (w2 + (size_t)z * D_FF * D_MODEL) : uw2;
    const float* __restrict__ bias = (z < N_EXPERTS) ? (b2 + (size_t)z * D_MODEL) : ub2;

    __shared__ int   s_tok[128];
    __shared__ float s_w[128];
    __shared__ int   s_row[128];
    __shared__ float As[128][16];
    __shared__ float Bs[16][128];

    const int tid = threadIdx.x;
    const int tx  = tid & 15;
    const int ty  = tid >> 4;

    if (tid < 128) {
        const int mm = m0 + tid;
        const int rr = roff + ((mm < cnt) ? mm : 0);
        s_row[tid] = rr;
        s_tok[tid] = g_assign_tok[rr];
        s_w[tid]   = g_assign_w[rr];
    }
    __syncthreads();

    float acc[8][8];
#pragma unroll
    for (int i = 0; i < 8; i++)
#pragma unroll
        for (int j = 0; j < 8; j++) acc[i][j] = 0.f;

    for (int k0 = 0; k0 < D_FF; k0 += 16) {
#pragma unroll
        for (int q = 0; q < 8; q++) {
            const int e = tid + q * 256;
            const int m = e >> 4, kk = e & 15;
            As[m][kk] = g_H[(size_t)s_row[m] * D_FF + k0 + kk];
        }
#pragma unroll
        for (int q = 0; q < 8; q++) {
            const int e = tid + q * 256;
            const int kk = e >> 7, d = e & 127;
            Bs[kk][d] = W[(size_t)(k0 + kk) * D_MODEL + d0 + d];
        }
        __syncthreads();
#pragma unroll
        for (int kk = 0; kk < 16; kk++) {
            float a[8], b[8];
#pragma unroll
            for (int i = 0; i < 8; i++) a[i] = As[ty + 16 * i][kk];
#pragma unroll
            for (int j = 0; j < 8; j++) b[j] = Bs[kk][tx + 16 * j];
#pragma unroll
            for (int i = 0; i < 8; i++)
#pragma unroll
                for (int j = 0; j < 8; j++)
                    acc[i][j] = fmaf(a[i], b[j], acc[i][j]);
        }
        __syncthreads();
    }

#pragma unroll
    for (int i = 0; i < 8; i++) {
        const int m = ty + 16 * i;
        if (m0 + m < cnt) {
            const int   tok = s_tok[m];
            const float wr  = s_w[m];
#pragma unroll
            for (int j = 0; j < 8; j++) {
                const int d = d0 + tx + 16 * j;
                atomicAdd(&out[(size_t)tok * D_MODEL + d], wr * (acc[i][j] + bias[d]));
            }
        }
    }
}

// ----------------------------- launch --------------------------------------
extern "C" void kernel_launch(void* const* d_in, const int* in_sizes, int n_in,
                              void* d_out, int out_size) {
    const float* x        = (const float*)d_in[0];
    const int*   task_ids = (const int*)  d_in[1];
    const float* temb     = (const float*)d_in[2];
    const float* gw       = (const float*)d_in[3];
    const float* gb       = (const float*)d_in[4];
    const float* w1       = (const float*)d_in[5];
    const float* b1       = (const float*)d_in[6];
    const float* w2       = (const float*)d_in[7];
    const float* b2       = (const float*)d_in[8];
    const float* uw1      = (const float*)d_in[9];
    const float* ub1      = (const float*)d_in[10];
    const float* uw2      = (const float*)d_in[11];
    const float* ub2      = (const float*)d_in[12];

    float* out        = (float*)d_out;
    float* out_logits = out + OUT_ELEMS;

    k_zero<<<OUT_ELEMS / 4 / 256, 256>>>((float4*)out);
    k_gate<<<TOK, 256>>>(x, task_ids, temb, gw, gb, out_logits);
    k_scan<<<1, 32>>>();
    k_build<<<N_EXPERTS + 1, 256>>>();
    k_ffn1<<<dim3(D_FF / 128, TOK / 128, N_EXPERTS + 1), 256>>>(x, w1, b1, uw1, ub1);
    k_ffn2<<<dim3(D_MODEL / 128, TOK / 128, N_EXPERTS + 1), 256>>>(out, w2, b2, uw2, ub2);
}

// round 5
// speedup vs baseline: 2.4420x; 2.4420x over previous
#include <cuda_runtime.h>
#include <cuda_bf16.h>
#include <math.h>
#include <stdint.h>

// ---------------------------------------------------------------------------
// TaskAwareMoE round 5: round-1 verified skeleton + mma.sync inner product.
// fp32 emulated as bf16 hi/lo in registers: A*B ~= Ah*Bh + Ah*Bl + Al*Bh.
// No cp.async, no ldmatrix, no pre-split scratch -> minimal delta vs round 1.
// ---------------------------------------------------------------------------

#define D_MODEL   512
#define D_FF      2048
#define N_EXPERTS 8
#define BATCH     8
#define SEQ       1024
#define TOK       (BATCH * SEQ)            // 8192
#define EXP_ROWS  (2 * TOK)                // 16384
#define TOT_ROWS  (EXP_ROWS + TOK)         // 24576
#define OUT_ELEMS (TOK * D_MODEL)          // 4,194,304
#define NGRP      (N_EXPERTS + 1)

// ----------------------------- static scratch ------------------------------
__device__ float g_H[(size_t)TOT_ROWS * D_FF];   // fp32 hidden activations
__device__ int   g_count[N_EXPERTS + 1];
__device__ int   g_offset[N_EXPERTS + 2];
__device__ int   g_tok_e0[TOK];
__device__ int   g_tok_e1[TOK];
__device__ float g_tok_p0[TOK];
__device__ float g_tok_p1[TOK];
__device__ float g_tok_om[TOK];
__device__ int   g_assign_tok[TOT_ROWS];
__device__ float g_assign_w[TOT_ROWS];

// ----------------------------- mma helpers ---------------------------------
__device__ __forceinline__ void mma16816(float d[4], const uint32_t a[4],
                                         uint32_t b0, uint32_t b1) {
    asm volatile(
        "mma.sync.aligned.m16n8k16.row.col.f32.bf16.bf16.f32 "
        "{%0,%1,%2,%3}, {%4,%5,%6,%7}, {%8,%9}, {%0,%1,%2,%3};"
        : "+f"(d[0]), "+f"(d[1]), "+f"(d[2]), "+f"(d[3])
        : "r"(a[0]), "r"(a[1]), "r"(a[2]), "r"(a[3]), "r"(b0), "r"(b1));
}

// split (x,y) fp32 pair into hi/lo bf16x2 packs (x in low half)
__device__ __forceinline__ void split2(float x, float y, uint32_t& hi, uint32_t& lo) {
    __nv_bfloat162 h = __floats2bfloat162_rn(x, y);
    hi = *(uint32_t*)&h;
    float rx = x - __bfloat162float(h.x);
    float ry = y - __bfloat162float(h.y);
    __nv_bfloat162 l = __floats2bfloat162_rn(rx, ry);
    lo = *(uint32_t*)&l;
}

// ----------------------------- init / zero ---------------------------------
__global__ void k_zero(float4* __restrict__ out4) {
    unsigned i = blockIdx.x * 256u + threadIdx.x;
    if (i < OUT_ELEMS / 4) out4[i] = make_float4(0.f, 0.f, 0.f, 0.f);
    if (blockIdx.x == 0 && threadIdx.x <= N_EXPERTS) g_count[threadIdx.x] = 0;
}

// ----------------------------- gating (round-1 verbatim) -------------------
__global__ void k_gate(const float* __restrict__ x,
                       const int*   __restrict__ task_ids,
                       const float* __restrict__ temb,
                       const float* __restrict__ gw,
                       const float* __restrict__ gb,
                       float* __restrict__ out_logits) {
    const int t   = blockIdx.x;
    const int tid = threadIdx.x;
    const int task = task_ids[t / SEQ];
    const float* xr = x    + (size_t)t    * D_MODEL;
    const float* tr = temb + (size_t)task * D_MODEL;

    float acc[N_EXPERTS];
#pragma unroll
    for (int e = 0; e < N_EXPERTS; e++) acc[e] = 0.f;
    for (int d = tid; d < 2 * D_MODEL; d += 256) {
        float v = (d < D_MODEL) ? xr[d] : tr[d - D_MODEL];
        const float* g = gw + (size_t)d * N_EXPERTS;
#pragma unroll
        for (int e = 0; e < N_EXPERTS; e++) acc[e] += v * g[e];
    }
#pragma unroll
    for (int e = 0; e < N_EXPERTS; e++)
#pragma unroll
        for (int off = 16; off > 0; off >>= 1)
            acc[e] += __shfl_down_sync(0xffffffffu, acc[e], off);

    __shared__ float s_acc[8][N_EXPERTS];
    const int warp = tid >> 5, lane = tid & 31;
    if (lane == 0)
#pragma unroll
        for (int e = 0; e < N_EXPERTS; e++) s_acc[warp][e] = acc[e];
    __syncthreads();

    if (tid == 0) {
        float lg[N_EXPERTS];
#pragma unroll
        for (int e = 0; e < N_EXPERTS; e++) {
            float s = gb[e];
#pragma unroll
            for (int w = 0; w < 8; w++) s += s_acc[w][e];
            lg[e] = s;
            out_logits[(size_t)t * N_EXPERTS + e] = s;
        }
        int e0 = 0; float v0 = lg[0];
#pragma unroll
        for (int e = 1; e < N_EXPERTS; e++) if (lg[e] > v0) { v0 = lg[e]; e0 = e; }
        int e1 = -1; float v1 = -1e30f;
#pragma unroll
        for (int e = 0; e < N_EXPERTS; e++)
            if (e != e0 && lg[e] > v1) { v1 = lg[e]; e1 = e; }
        float ex = expf(v1 - v0);
        float p0 = 1.f / (1.f + ex);
        g_tok_e0[t] = e0;  g_tok_e1[t] = e1;
        g_tok_p0[t] = p0;  g_tok_p1[t] = ex / (1.f + ex);
        g_tok_om[t] = 1.f - p0;
        atomicAdd(&g_count[e0], 1);
        atomicAdd(&g_count[e1], 1);
    }
}

__global__ void k_scan() {
    if (blockIdx.x == 0 && threadIdx.x == 0) {
        int o = 0;
        for (int e = 0; e < N_EXPERTS; e++) { g_offset[e] = o; o += g_count[e]; }
        g_offset[N_EXPERTS]     = o;
        g_offset[N_EXPERTS + 1] = o + TOK;
    }
}

// ----------------------------- routing lists (round-1 verbatim) ------------
__global__ void k_build() {
    const int e   = blockIdx.x;
    const int tid = threadIdx.x;

    if (e == N_EXPERTS) {
        const int base = g_offset[N_EXPERTS];
        for (int t = tid; t < TOK; t += 256) {
            g_assign_tok[base + t] = t;
            g_assign_w[base + t]   = g_tok_om[t];
        }
        return;
    }

    __shared__ int s_scan[256];
    __shared__ int s_base;
    if (tid == 0) s_base = g_offset[e];
    __syncthreads();

    for (int t0 = 0; t0 < TOK; t0 += 256) {
        const int t = t0 + tid;
        int flag = 0; float w = 0.f;
        if (g_tok_e0[t] == e)      { flag = 1; w = g_tok_p0[t]; }
        else if (g_tok_e1[t] == e) { flag = 1; w = g_tok_p1[t]; }

        s_scan[tid] = flag;
        __syncthreads();
        for (int off = 1; off < 256; off <<= 1) {
            int v = (tid >= off) ? s_scan[tid - off] : 0;
            __syncthreads();
            s_scan[tid] += v;
            __syncthreads();
        }
        const int incl  = s_scan[tid];
        const int total = s_scan[255];
        const int base  = s_base;
        __syncthreads();
        if (flag) {
            const int pos = base + incl - 1;
            g_assign_tok[pos] = t;
            g_assign_w[pos]   = w;
        }
        if (tid == 0) s_base = base + total;
        __syncthreads();
    }
}

// ---------------------------------------------------------------------------
// Fragment build + 3-term MMA over one BK=16 chunk held in padded fp32 smem.
// 8 warps (2x4), warp tile 64x32; per-thread g=lane>>2, c=lane&3.
// ---------------------------------------------------------------------------
__device__ __forceinline__ void mma_chunk(float d[4][4][4],
                                          const float As[128][18],
                                          const float Bs[16][132],
                                          int wm, int wn, int g, int c) {
    uint32_t ah[4][4], al[4][4];
#pragma unroll
    for (int mt = 0; mt < 4; mt++) {
        const int r0 = wm * 64 + mt * 16 + g;
        const float2* A0 = (const float2*)&As[r0][0];
        const float2* A1 = (const float2*)&As[r0 + 8][0];
        float2 v0 = A0[c];
        float2 v1 = A1[c];
        float2 v2 = A0[c + 4];
        float2 v3 = A1[c + 4];
        split2(v0.x, v0.y, ah[mt][0], al[mt][0]);
        split2(v1.x, v1.y, ah[mt][1], al[mt][1]);
        split2(v2.x, v2.y, ah[mt][2], al[mt][2]);
        split2(v3.x, v3.y, ah[mt][3], al[mt][3]);
    }
    uint32_t bh[4][2], bl[4][2];
#pragma unroll
    for (int nt = 0; nt < 4; nt++) {
        const int n = wn * 32 + nt * 8 + g;
        split2(Bs[2 * c][n],     Bs[2 * c + 1][n], bh[nt][0], bl[nt][0]);
        split2(Bs[2 * c + 8][n], Bs[2 * c + 9][n], bh[nt][1], bl[nt][1]);
    }
#pragma unroll
    for (int mt = 0; mt < 4; mt++)
#pragma unroll
        for (int nt = 0; nt < 4; nt++) {
            mma16816(d[mt][nt], ah[mt], bh[nt][0], bh[nt][1]);
            mma16816(d[mt][nt], ah[mt], bl[nt][0], bl[nt][1]);
            mma16816(d[mt][nt], al[mt], bh[nt][0], bh[nt][1]);
        }
}

// ----------------------------- FFN1: H = gelu(X @ W1 + b1) -----------------
// grid (D_FF/128, 64, 9), 256 threads.
__global__ void __launch_bounds__(256)
k_ffn1(const float* __restrict__ x,
       const float* __restrict__ w1,  const float* __restrict__ b1,
       const float* __restrict__ uw1, const float* __restrict__ ub1) {
    const int z    = blockIdx.z;
    const int roff = g_offset[z];
    const int cnt  = g_offset[z + 1] - roff;
    const int m0   = blockIdx.y * 128;
    if (m0 >= cnt) return;
    const int f0   = blockIdx.x * 128;

    const float* __restrict__ W    = (z < N_EXPERTS) ? (w1 + (size_t)z * D_MODEL * D_FF) : uw1;
    const float* __restrict__ bias = (z < N_EXPERTS) ? (b1 + (size_t)z * D_FF) : ub1;

    __shared__ int   s_tok[128];
    __shared__ float As[128][18];
    __shared__ float Bs[16][132];

    const int tid  = threadIdx.x;
    const int wid  = tid >> 5;
    const int lane = tid & 31;
    const int wm = wid >> 2, wn = wid & 3;
    const int g = lane >> 2, c = lane & 3;

    if (tid < 128) {
        const int mm = m0 + tid;
        s_tok[tid] = g_assign_tok[roff + ((mm < cnt) ? mm : 0)];
    }
    __syncthreads();

    // per-thread fixed load indices
    const int kkA  = tid & 15;      // As column
    const int fB   = tid & 127;     // Bs column
    const int kkB0 = tid >> 7;      // 0/1
    unsigned arow[8];
#pragma unroll
    for (int q = 0; q < 8; q++)
        arow[q] = (unsigned)s_tok[(tid >> 4) + 16 * q] * (unsigned)D_MODEL;

    float d[4][4][4];
#pragma unroll
    for (int a = 0; a < 4; a++)
#pragma unroll
        for (int b = 0; b < 4; b++)
#pragma unroll
            for (int e = 0; e < 4; e++) d[a][b][e] = 0.f;

    float pa[8], pb[8];
#pragma unroll
    for (int q = 0; q < 8; q++) pa[q] = x[(size_t)arow[q] + kkA];
#pragma unroll
    for (int q = 0; q < 8; q++) pb[q] = W[(size_t)(kkB0 + 2 * q) * D_FF + f0 + fB];

    constexpr int NCH = D_MODEL / 16;   // 32
    for (int ch = 0; ch < NCH; ch++) {
        __syncthreads();                 // previous compute done
#pragma unroll
        for (int q = 0; q < 8; q++) As[(tid >> 4) + 16 * q][kkA] = pa[q];
#pragma unroll
        for (int q = 0; q < 8; q++) Bs[kkB0 + 2 * q][fB] = pb[q];
        __syncthreads();
        if (ch + 1 < NCH) {
            const int k0 = (ch + 1) * 16;
#pragma unroll
            for (int q = 0; q < 8; q++) pa[q] = x[(size_t)arow[q] + k0 + kkA];
#pragma unroll
            for (int q = 0; q < 8; q++) pb[q] = W[(size_t)(k0 + kkB0 + 2 * q) * D_FF + f0 + fB];
        }
        mma_chunk(d, As, Bs, wm, wn, g, c);
    }

    // epilogue: bias + exact gelu -> fp32 H
#pragma unroll
    for (int mt = 0; mt < 4; mt++)
#pragma unroll
        for (int half = 0; half < 2; half++) {
            const int m = wm * 64 + mt * 16 + g + half * 8;
            if (m0 + m >= cnt) continue;
            float* hrow = g_H + (size_t)(roff + m0 + m) * D_FF;
#pragma unroll
            for (int nt = 0; nt < 4; nt++) {
                const int f = f0 + wn * 32 + nt * 8 + 2 * c;
                float v0 = d[mt][nt][half * 2 + 0] + bias[f];
                float v1 = d[mt][nt][half * 2 + 1] + bias[f + 1];
                v0 = 0.5f * v0 * (1.0f + erff(v0 * 0.70710678118654752f));
                v1 = 0.5f * v1 * (1.0f + erff(v1 * 0.70710678118654752f));
                *(float2*)(hrow + f) = make_float2(v0, v1);
            }
        }
}

// ----------------------------- FFN2: out += w*(H @ W2 + b2) ----------------
// grid (D_MODEL/128, 64, 9)
__global__ void __launch_bounds__(256)
k_ffn2(float* __restrict__ out,
       const float* __restrict__ w2,  const float* __restrict__ b2,
       const float* __restrict__ uw2, const float* __restrict__ ub2) {
    const int z    = blockIdx.z;
    const int roff = g_offset[z];
    const int cnt  = g_offset[z + 1] - roff;
    const int m0   = blockIdx.y * 128;
    if (m0 >= cnt) return;
    const int d0   = blockIdx.x * 128;

    const float* __restrict__ W    = (z < N_EXPERTS) ? (w2 + (size_t)z * D_FF * D_MODEL) : uw2;
    const float* __restrict__ bias = (z < N_EXPERTS) ? (b2 + (size_t)z * D_MODEL) : ub2;

    __shared__ int   s_tok[128];
    __shared__ float s_w[128];
    __shared__ int   s_row[128];
    __shared__ float As[128][18];
    __shared__ float Bs[16][132];

    const int tid  = threadIdx.x;
    const int wid  = tid >> 5;
    const int lane = tid & 31;
    const int wm = wid >> 2, wn = wid & 3;
    const int g = lane >> 2, c = lane & 3;

    if (tid < 128) {
        const int mm = m0 + tid;
        const int rr = roff + ((mm < cnt) ? mm : 0);
        s_row[tid] = rr;
        s_tok[tid] = g_assign_tok[rr];
        s_w[tid]   = g_assign_w[rr];
    }
    __syncthreads();

    const int kkA  = tid & 15;
    const int fB   = tid & 127;
    const int kkB0 = tid >> 7;
    unsigned arow[8];
#pragma unroll
    for (int q = 0; q < 8; q++)
        arow[q] = (unsigned)s_row[(tid >> 4) + 16 * q] * (unsigned)D_FF;

    float d[4][4][4];
#pragma unroll
    for (int a = 0; a < 4; a++)
#pragma unroll
        for (int b = 0; b < 4; b++)
#pragma unroll
            for (int e = 0; e < 4; e++) d[a][b][e] = 0.f;

    float pa[8], pb[8];
#pragma unroll
    for (int q = 0; q < 8; q++) pa[q] = g_H[(size_t)arow[q] + kkA];
#pragma unroll
    for (int q = 0; q < 8; q++) pb[q] = W[(size_t)(kkB0 + 2 * q) * D_MODEL + d0 + fB];

    constexpr int NCH = D_FF / 16;   // 128
    for (int ch = 0; ch < NCH; ch++) {
        __syncthreads();
#pragma unroll
        for (int q = 0; q < 8; q++) As[(tid >> 4) + 16 * q][kkA] = pa[q];
#pragma unroll
        for (int q = 0; q < 8; q++) Bs[kkB0 + 2 * q][fB] = pb[q];
        __syncthreads();
        if (ch + 1 < NCH) {
            const int k0 = (ch + 1) * 16;
#pragma unroll
            for (int q = 0; q < 8; q++) pa[q] = g_H[(size_t)arow[q] + k0 + kkA];
#pragma unroll
            for (int q = 0; q < 8; q++) pb[q] = W[(size_t)(k0 + kkB0 + 2 * q) * D_MODEL + d0 + fB];
        }
        mma_chunk(d, As, Bs, wm, wn, g, c);
    }

    // epilogue: weighted atomic accumulation
#pragma unroll
    for (int mt = 0; mt < 4; mt++)
#pragma unroll
        for (int half = 0; half < 2; half++) {
            const int m = wm * 64 + mt * 16 + g + half * 8;
            if (m0 + m >= cnt) continue;
            const int   tok = s_tok[m];
            const float wr  = s_w[m];
            float* orow = out + (size_t)tok * D_MODEL;
#pragma unroll
            for (int nt = 0; nt < 4; nt++) {
                const int dd = d0 + wn * 32 + nt * 8 + 2 * c;
                atomicAdd(&orow[dd],     wr * (d[mt][nt][half * 2 + 0] + bias[dd]));
                atomicAdd(&orow[dd + 1], wr * (d[mt][nt][half * 2 + 1] + bias[dd + 1]));
            }
        }
}

// ----------------------------- launch --------------------------------------
extern "C" void kernel_launch(void* const* d_in, const int* in_sizes, int n_in,
                              void* d_out, int out_size) {
    const float* x        = (const float*)d_in[0];
    const int*   task_ids = (const int*)  d_in[1];
    const float* temb     = (const float*)d_in[2];
    const float* gw       = (const float*)d_in[3];
    const float* gb       = (const float*)d_in[4];
    const float* w1       = (const float*)d_in[5];
    const float* b1       = (const float*)d_in[6];
    const float* w2       = (const float*)d_in[7];
    const float* b2       = (const float*)d_in[8];
    const float* uw1      = (const float*)d_in[9];
    const float* ub1      = (const float*)d_in[10];
    const float* uw2      = (const float*)d_in[11];
    const float* ub2      = (const float*)d_in[12];

    float* out        = (float*)d_out;
    float* out_logits = out + OUT_ELEMS;

    k_zero<<<OUT_ELEMS / 4 / 256, 256>>>((float4*)out);
    k_gate<<<TOK, 256>>>(x, task_ids, temb, gw, gb, out_logits);
    k_scan<<<1, 32>>>();
    k_build<<<NGRP, 256>>>();
    k_ffn1<<<dim3(D_FF / 128, TOK / 128, NGRP), 256>>>(x, w1, b1, uw1, ub1);
    k_ffn2<<<dim3(D_MODEL / 128, TOK / 128, NGRP), 256>>>(out, w2, b2, uw2, ub2);
}

// round 6
// speedup vs baseline: 2.6770x; 1.0962x over previous
#include <cuda_runtime.h>
#include <cuda_bf16.h>
#include <math.h>
#include <stdint.h>

// ---------------------------------------------------------------------------
// TaskAwareMoE round 6: mma.sync bf16 grouped GEMMs; hi/lo split moved to
// staging (smem holds packed bf16x2), fragment build = pure LDS.
//   A*B ~= Ah*Bh + Ah*Bl + Al*Bh  (err ~2^-17)
// ---------------------------------------------------------------------------

#define D_MODEL   512
#define D_FF      2048
#define N_EXPERTS 8
#define BATCH     8
#define SEQ       1024
#define TOK       (BATCH * SEQ)            // 8192
#define EXP_ROWS  (2 * TOK)                // 16384
#define TOT_ROWS  (EXP_ROWS + TOK)         // 24576
#define OUT_ELEMS (TOK * D_MODEL)          // 4,194,304
#define NGRP      (N_EXPERTS + 1)

#define ASTRIDE 12      // uint32 words per A row  (8 used + 4 pad) -> bank-free
#define BSTRIDE 136     // uint32 words per B k-pair row (128 used + 8 pad)

// ----------------------------- static scratch ------------------------------
__device__ float g_H[(size_t)TOT_ROWS * D_FF];   // fp32 hidden activations
__device__ int   g_count[N_EXPERTS + 1];
__device__ int   g_offset[N_EXPERTS + 2];
__device__ int   g_tok_e0[TOK];
__device__ int   g_tok_e1[TOK];
__device__ float g_tok_p0[TOK];
__device__ float g_tok_p1[TOK];
__device__ float g_tok_om[TOK];
__device__ int   g_assign_tok[TOT_ROWS];
__device__ float g_assign_w[TOT_ROWS];

// ----------------------------- mma helpers ---------------------------------
__device__ __forceinline__ void mma16816(float d[4], const uint32_t a[4],
                                         uint32_t b0, uint32_t b1) {
    asm volatile(
        "mma.sync.aligned.m16n8k16.row.col.f32.bf16.bf16.f32 "
        "{%0,%1,%2,%3}, {%4,%5,%6,%7}, {%8,%9}, {%0,%1,%2,%3};"
        : "+f"(d[0]), "+f"(d[1]), "+f"(d[2]), "+f"(d[3])
        : "r"(a[0]), "r"(a[1]), "r"(a[2]), "r"(a[3]), "r"(b0), "r"(b1));
}

// split (x,y) fp32 pair into hi/lo bf16x2 packs (x in low half)
__device__ __forceinline__ void split2(float x, float y, uint32_t& hi, uint32_t& lo) {
    __nv_bfloat162 h = __floats2bfloat162_rn(x, y);
    hi = *(uint32_t*)&h;
    float rx = x - __bfloat162float(h.x);
    float ry = y - __bfloat162float(h.y);
    __nv_bfloat162 l = __floats2bfloat162_rn(rx, ry);
    lo = *(uint32_t*)&l;
}

// ----------------------------- init / zero ---------------------------------
__global__ void k_zero(float4* __restrict__ out4) {
    unsigned i = blockIdx.x * 256u + threadIdx.x;
    if (i < OUT_ELEMS / 4) out4[i] = make_float4(0.f, 0.f, 0.f, 0.f);
    if (blockIdx.x == 0 && threadIdx.x <= N_EXPERTS) g_count[threadIdx.x] = 0;
}

// ----------------------------- gating --------------------------------------
__global__ void k_gate(const float* __restrict__ x,
                       const int*   __restrict__ task_ids,
                       const float* __restrict__ temb,
                       const float* __restrict__ gw,
                       const float* __restrict__ gb,
                       float* __restrict__ out_logits) {
    const int t   = blockIdx.x;
    const int tid = threadIdx.x;
    const int task = task_ids[t / SEQ];
    const float* xr = x    + (size_t)t    * D_MODEL;
    const float* tr = temb + (size_t)task * D_MODEL;

    float acc[N_EXPERTS];
#pragma unroll
    for (int e = 0; e < N_EXPERTS; e++) acc[e] = 0.f;
    for (int d = tid; d < 2 * D_MODEL; d += 256) {
        float v = (d < D_MODEL) ? xr[d] : tr[d - D_MODEL];
        const float* g = gw + (size_t)d * N_EXPERTS;
#pragma unroll
        for (int e = 0; e < N_EXPERTS; e++) acc[e] += v * g[e];
    }
#pragma unroll
    for (int e = 0; e < N_EXPERTS; e++)
#pragma unroll
        for (int off = 16; off > 0; off >>= 1)
            acc[e] += __shfl_down_sync(0xffffffffu, acc[e], off);

    __shared__ float s_acc[8][N_EXPERTS];
    const int warp = tid >> 5, lane = tid & 31;
    if (lane == 0)
#pragma unroll
        for (int e = 0; e < N_EXPERTS; e++) s_acc[warp][e] = acc[e];
    __syncthreads();

    if (tid == 0) {
        float lg[N_EXPERTS];
#pragma unroll
        for (int e = 0; e < N_EXPERTS; e++) {
            float s = gb[e];
#pragma unroll
            for (int w = 0; w < 8; w++) s += s_acc[w][e];
            lg[e] = s;
            out_logits[(size_t)t * N_EXPERTS + e] = s;
        }
        int e0 = 0; float v0 = lg[0];
#pragma unroll
        for (int e = 1; e < N_EXPERTS; e++) if (lg[e] > v0) { v0 = lg[e]; e0 = e; }
        int e1 = -1; float v1 = -1e30f;
#pragma unroll
        for (int e = 0; e < N_EXPERTS; e++)
            if (e != e0 && lg[e] > v1) { v1 = lg[e]; e1 = e; }
        float ex = expf(v1 - v0);
        float p0 = 1.f / (1.f + ex);
        g_tok_e0[t] = e0;  g_tok_e1[t] = e1;
        g_tok_p0[t] = p0;  g_tok_p1[t] = ex / (1.f + ex);
        g_tok_om[t] = 1.f - p0;
        atomicAdd(&g_count[e0], 1);
        atomicAdd(&g_count[e1], 1);
    }
}

__global__ void k_scan() {
    if (blockIdx.x == 0 && threadIdx.x == 0) {
        int o = 0;
        for (int e = 0; e < N_EXPERTS; e++) { g_offset[e] = o; o += g_count[e]; }
        g_offset[N_EXPERTS]     = o;
        g_offset[N_EXPERTS + 1] = o + TOK;
    }
}

// ballot-scan routing-list builder (deterministic)
__global__ void k_build() {
    const int e   = blockIdx.x;
    const int tid = threadIdx.x;
    if (e == N_EXPERTS) {
        const int base = g_offset[N_EXPERTS];
        for (int t = tid; t < TOK; t += 256) {
            g_assign_tok[base + t] = t;
            g_assign_w[base + t]   = g_tok_om[t];
        }
        return;
    }
    __shared__ int s_wtot[8];
    __shared__ int s_base;
    const int warp = tid >> 5, lane = tid & 31;
    if (tid == 0) s_base = g_offset[e];
    __syncthreads();

    for (int t0 = 0; t0 < TOK; t0 += 256) {
        const int t = t0 + tid;
        int flag = 0; float w = 0.f;
        if (g_tok_e0[t] == e)      { flag = 1; w = g_tok_p0[t]; }
        else if (g_tok_e1[t] == e) { flag = 1; w = g_tok_p1[t]; }
        unsigned bal = __ballot_sync(0xffffffffu, flag);
        int wpre = __popc(bal & ((1u << lane) - 1u));
        if (lane == 0) s_wtot[warp] = __popc(bal);
        __syncthreads();
        int wb = 0, tot = 0;
#pragma unroll
        for (int i = 0; i < 8; i++) { int v = s_wtot[i]; if (i < warp) wb += v; tot += v; }
        const int base = s_base;
        __syncthreads();
        if (flag) {
            const int pos = base + wb + wpre;
            g_assign_tok[pos] = t;
            g_assign_w[pos]   = w;
        }
        if (tid == 0) s_base = base + tot;
        __syncthreads();
    }
}

// ---------------------------------------------------------------------------
// MMA over one BK=16 chunk held as packed bf16x2 hi/lo in smem.
// 8 warps (2x4), warp tile 64x32; g = lane>>2 (row/col), c = lane&3 (k-pair).
// ---------------------------------------------------------------------------
__device__ __forceinline__ void mma_chunk(float d[4][4][4],
                                          const uint32_t* Ah, const uint32_t* Al,
                                          const uint32_t* Bh, const uint32_t* Bl,
                                          int wm, int wn, int g, int c) {
    uint32_t ah[4][4], al[4][4];
#pragma unroll
    for (int mt = 0; mt < 4; mt++) {
        const int r0 = (wm * 64 + mt * 16 + g) * ASTRIDE;
        const int r1 = r0 + 8 * ASTRIDE;
        ah[mt][0] = Ah[r0 + c];     al[mt][0] = Al[r0 + c];
        ah[mt][1] = Ah[r1 + c];     al[mt][1] = Al[r1 + c];
        ah[mt][2] = Ah[r0 + c + 4]; al[mt][2] = Al[r0 + c + 4];
        ah[mt][3] = Ah[r1 + c + 4]; al[mt][3] = Al[r1 + c + 4];
    }
    uint32_t bh[4][2], bl[4][2];
#pragma unroll
    for (int nt = 0; nt < 4; nt++) {
        const int n = wn * 32 + nt * 8 + g;
        bh[nt][0] = Bh[c * BSTRIDE + n];        bl[nt][0] = Bl[c * BSTRIDE + n];
        bh[nt][1] = Bh[(c + 4) * BSTRIDE + n];  bl[nt][1] = Bl[(c + 4) * BSTRIDE + n];
    }
#pragma unroll
    for (int mt = 0; mt < 4; mt++)
#pragma unroll
        for (int nt = 0; nt < 4; nt++) {
            mma16816(d[mt][nt], ah[mt], bh[nt][0], bh[nt][1]);
            mma16816(d[mt][nt], ah[mt], bl[nt][0], bl[nt][1]);
            mma16816(d[mt][nt], al[mt], bh[nt][0], bh[nt][1]);
        }
}

// ----------------------------- FFN1: H = gelu(X @ W1 + b1) -----------------
// grid (D_FF/128, 64, 9), 256 threads.
__global__ void __launch_bounds__(256)
k_ffn1(const float* __restrict__ x,
       const float* __restrict__ w1,  const float* __restrict__ b1,
       const float* __restrict__ uw1, const float* __restrict__ ub1) {
    const int z    = blockIdx.z;
    const int roff = g_offset[z];
    const int cnt  = g_offset[z + 1] - roff;
    const int m0   = blockIdx.y * 128;
    if (m0 >= cnt) return;
    const int f0   = blockIdx.x * 128;

    const float* __restrict__ W    = (z < N_EXPERTS) ? (w1 + (size_t)z * D_MODEL * D_FF) : uw1;
    const float* __restrict__ bias = (z < N_EXPERTS) ? (b1 + (size_t)z * D_FF) : ub1;

    __shared__ int      s_tok[128];
    __shared__ uint32_t As_h[128 * ASTRIDE];
    __shared__ uint32_t As_l[128 * ASTRIDE];
    __shared__ uint32_t Bs_h[8 * BSTRIDE];
    __shared__ uint32_t Bs_l[8 * BSTRIDE];

    const int tid  = threadIdx.x;
    const int wid  = tid >> 5;
    const int lane = tid & 31;
    const int wm = wid >> 2, wn = wid & 3;
    const int g = lane >> 2, c = lane & 3;

    if (tid < 128) {
        const int mm = m0 + tid;
        s_tok[tid] = g_assign_tok[roff + ((mm < cnt) ? mm : 0)];
    }
    __syncthreads();

    // per-thread staging indices: A -> 4 (row, kpair); B -> 4 (kpair, col)
    int   rA[4], kpA[4], kpB[4], fB[4];
    unsigned arow[4];
#pragma unroll
    for (int q = 0; q < 4; q++) {
        const int ia = tid + q * 256;
        rA[q]  = ia >> 3;  kpA[q] = ia & 7;
        arow[q] = (unsigned)s_tok[rA[q]] * (unsigned)D_MODEL;
        kpB[q] = ia >> 7;  fB[q]  = ia & 127;
    }

    float d[4][4][4];
#pragma unroll
    for (int a = 0; a < 4; a++)
#pragma unroll
        for (int b = 0; b < 4; b++)
#pragma unroll
            for (int e = 0; e < 4; e++) d[a][b][e] = 0.f;

    float2 pa[4];
    float  pb0[4], pb1[4];
#pragma unroll
    for (int q = 0; q < 4; q++) {
        pa[q]  = *(const float2*)(x + (size_t)arow[q] + 2 * kpA[q]);
        pb0[q] = W[(size_t)(2 * kpB[q])     * D_FF + f0 + fB[q]];
        pb1[q] = W[(size_t)(2 * kpB[q] + 1) * D_FF + f0 + fB[q]];
    }

    constexpr int NCH = D_MODEL / 16;   // 32
    for (int ch = 0; ch < NCH; ch++) {
        __syncthreads();                 // previous compute done
#pragma unroll
        for (int q = 0; q < 4; q++) {
            uint32_t h, l;
            split2(pa[q].x, pa[q].y, h, l);
            As_h[rA[q] * ASTRIDE + kpA[q]] = h;
            As_l[rA[q] * ASTRIDE + kpA[q]] = l;
            split2(pb0[q], pb1[q], h, l);
            Bs_h[kpB[q] * BSTRIDE + fB[q]] = h;
            Bs_l[kpB[q] * BSTRIDE + fB[q]] = l;
        }
        __syncthreads();
        if (ch + 1 < NCH) {
            const int k0 = (ch + 1) * 16;
#pragma unroll
            for (int q = 0; q < 4; q++) {
                pa[q]  = *(const float2*)(x + (size_t)arow[q] + k0 + 2 * kpA[q]);
                pb0[q] = W[(size_t)(k0 + 2 * kpB[q])     * D_FF + f0 + fB[q]];
                pb1[q] = W[(size_t)(k0 + 2 * kpB[q] + 1) * D_FF + f0 + fB[q]];
            }
        }
        mma_chunk(d, As_h, As_l, Bs_h, Bs_l, wm, wn, g, c);
    }

    // epilogue: bias + exact gelu -> fp32 H
#pragma unroll
    for (int mt = 0; mt < 4; mt++)
#pragma unroll
        for (int half = 0; half < 2; half++) {
            const int m = wm * 64 + mt * 16 + g + half * 8;
            if (m0 + m >= cnt) continue;
            float* hrow = g_H + (size_t)(roff + m0 + m) * D_FF;
#pragma unroll
            for (int nt = 0; nt < 4; nt++) {
                const int f = f0 + wn * 32 + nt * 8 + 2 * c;
                float v0 = d[mt][nt][half * 2 + 0] + bias[f];
                float v1 = d[mt][nt][half * 2 + 1] + bias[f + 1];
                v0 = 0.5f * v0 * (1.0f + erff(v0 * 0.70710678118654752f));
                v1 = 0.5f * v1 * (1.0f + erff(v1 * 0.70710678118654752f));
                *(float2*)(hrow + f) = make_float2(v0, v1);
            }
        }
}

// ----------------------------- FFN2: out += w*(H @ W2 + b2) ----------------
// grid (D_MODEL/128, 64, 9)
__global__ void __launch_bounds__(256)
k_ffn2(float* __restrict__ out,
       const float* __restrict__ w2,  const float* __restrict__ b2,
       const float* __restrict__ uw2, const float* __restrict__ ub2) {
    const int z    = blockIdx.z;
    const int roff = g_offset[z];
    const int cnt  = g_offset[z + 1] - roff;
    const int m0   = blockIdx.y * 128;
    if (m0 >= cnt) return;
    const int d0   = blockIdx.x * 128;

    const float* __restrict__ W    = (z < N_EXPERTS) ? (w2 + (size_t)z * D_FF * D_MODEL) : uw2;
    const float* __restrict__ bias = (z < N_EXPERTS) ? (b2 + (size_t)z * D_MODEL) : ub2;

    __shared__ int      s_tok[128];
    __shared__ float    s_w[128];
    __shared__ uint32_t As_h[128 * ASTRIDE];
    __shared__ uint32_t As_l[128 * ASTRIDE];
    __shared__ uint32_t Bs_h[8 * BSTRIDE];
    __shared__ uint32_t Bs_l[8 * BSTRIDE];

    const int tid  = threadIdx.x;
    const int wid  = tid >> 5;
    const int lane = tid & 31;
    const int wm = wid >> 2, wn = wid & 3;
    const int g = lane >> 2, c = lane & 3;

    if (tid < 128) {
        const int mm = m0 + tid;
        const int rr = roff + ((mm < cnt) ? mm : 0);
        s_tok[tid] = g_assign_tok[rr];
        s_w[tid]   = g_assign_w[rr];
    }
    __syncthreads();

    int   rA[4], kpA[4], kpB[4], fB[4];
    unsigned arow[4];
#pragma unroll
    for (int q = 0; q < 4; q++) {
        const int ia = tid + q * 256;
        rA[q]  = ia >> 3;  kpA[q] = ia & 7;
        const int mm = m0 + rA[q];
        arow[q] = (unsigned)(roff + ((mm < cnt) ? mm : m0)) * (unsigned)D_FF;
        kpB[q] = ia >> 7;  fB[q]  = ia & 127;
    }

    float d[4][4][4];
#pragma unroll
    for (int a = 0; a < 4; a++)
#pragma unroll
        for (int b = 0; b < 4; b++)
#pragma unroll
            for (int e = 0; e < 4; e++) d[a][b][e] = 0.f;

    float2 pa[4];
    float  pb0[4], pb1[4];
#pragma unroll
    for (int q = 0; q < 4; q++) {
        pa[q]  = *(const float2*)(g_H + (size_t)arow[q] + 2 * kpA[q]);
        pb0[q] = W[(size_t)(2 * kpB[q])     * D_MODEL + d0 + fB[q]];
        pb1[q] = W[(size_t)(2 * kpB[q] + 1) * D_MODEL + d0 + fB[q]];
    }

    constexpr int NCH = D_FF / 16;   // 128
    for (int ch = 0; ch < NCH; ch++) {
        __syncthreads();
#pragma unroll
        for (int q = 0; q < 4; q++) {
            uint32_t h, l;
            split2(pa[q].x, pa[q].y, h, l);
            As_h[rA[q] * ASTRIDE + kpA[q]] = h;
            As_l[rA[q] * ASTRIDE + kpA[q]] = l;
            split2(pb0[q], pb1[q], h, l);
            Bs_h[kpB[q] * BSTRIDE + fB[q]] = h;
            Bs_l[kpB[q] * BSTRIDE + fB[q]] = l;
        }
        __syncthreads();
        if (ch + 1 < NCH) {
            const int k0 = (ch + 1) * 16;
#pragma unroll
            for (int q = 0; q < 4; q++) {
                pa[q]  = *(const float2*)(g_H + (size_t)arow[q] + k0 + 2 * kpA[q]);
                pb0[q] = W[(size_t)(k0 + 2 * kpB[q])     * D_MODEL + d0 + fB[q]];
                pb1[q] = W[(size_t)(k0 + 2 * kpB[q] + 1) * D_MODEL + d0 + fB[q]];
            }
        }
        mma_chunk(d, As_h, As_l, Bs_h, Bs_l, wm, wn, g, c);
    }

    // epilogue: weighted atomic accumulation
#pragma unroll
    for (int mt = 0; mt < 4; mt++)
#pragma unroll
        for (int half = 0; half < 2; half++) {
            const int m = wm * 64 + mt * 16 + g + half * 8;
            if (m0 + m >= cnt) continue;
            const int   tok = s_tok[m];
            const float wr  = s_w[m];
            float* orow = out + (size_t)tok * D_MODEL;
#pragma unroll
            for (int nt = 0; nt < 4; nt++) {
                const int dd = d0 + wn * 32 + nt * 8 + 2 * c;
                atomicAdd(&orow[dd],     wr * (d[mt][nt][half * 2 + 0] + bias[dd]));
                atomicAdd(&orow[dd + 1], wr * (d[mt][nt][half * 2 + 1] + bias[dd + 1]));
            }
        }
}

// ----------------------------- launch --------------------------------------
extern "C" void kernel_launch(void* const* d_in, const int* in_sizes, int n_in,
                              void* d_out, int out_size) {
    const float* x        = (const float*)d_in[0];
    const int*   task_ids = (const int*)  d_in[1];
    const float* temb     = (const float*)d_in[2];
    const float* gw       = (const float*)d_in[3];
    const float* gb       = (const float*)d_in[4];
    const float* w1       = (const float*)d_in[5];
    const float* b1       = (const float*)d_in[6];
    const float* w2       = (const float*)d_in[7];
    const float* b2       = (const float*)d_in[8];
    const float* uw1      = (const float*)d_in[9];
    const float* ub1      = (const float*)d_in[10];
    const float* uw2      = (const float*)d_in[11];
    const float* ub2      = (const float*)d_in[12];

    float* out        = (float*)d_out;
    float* out_logits = out + OUT_ELEMS;

    k_zero<<<OUT_ELEMS / 4 / 256, 256>>>((float4*)out);
    k_gate<<<TOK, 256>>>(x, task_ids, temb, gw, gb, out_logits);
    k_scan<<<1, 32>>>();
    k_build<<<NGRP, 256>>>();
    k_ffn1<<<dim3(D_FF / 128, TOK / 128, NGRP), 256>>>(x, w1, b1, uw1, ub1);
    k_ffn2<<<dim3(D_MODEL / 128, TOK / 128, NGRP), 256>>>(out, w2, b2, uw2, ub2);
}

// round 7
// speedup vs baseline: 2.9799x; 1.1132x over previous
#include <cuda_runtime.h>
#include <cuda_bf16.h>
#include <math.h>
#include <stdint.h>

// ---------------------------------------------------------------------------
// TaskAwareMoE round 7: double-buffered stages (1 barrier/chunk), packed hi/lo
// H storage (no re-split in FFN2), atomic routing placement.
//   A*B ~= Ah*Bh + Ah*Bl + Al*Bh  (err ~2^-17)
// ---------------------------------------------------------------------------

#define D_MODEL   512
#define D_FF      2048
#define N_EXPERTS 8
#define BATCH     8
#define SEQ       1024
#define TOK       (BATCH * SEQ)            // 8192
#define EXP_ROWS  (2 * TOK)                // 16384
#define TOT_ROWS  (EXP_ROWS + TOK)         // 24576
#define OUT_ELEMS (TOK * D_MODEL)          // 4,194,304
#define NGRP      (N_EXPERTS + 1)
#define HKP       (D_FF / 2)               // 1024 k-pairs per H row

#define ASTRIDE 12      // uint32 words per A row  (8 used + 4 pad) -> bank-free
#define BSTRIDE 136     // uint32 words per B k-pair row (128 used + 8 pad)

// ----------------------------- static scratch ------------------------------
__device__ uint32_t g_Hh[(size_t)TOT_ROWS * HKP];  // packed bf16x2 hi pairs
__device__ uint32_t g_Hl[(size_t)TOT_ROWS * HKP];  // packed bf16x2 lo pairs
__device__ int   g_count[N_EXPERTS + 1];
__device__ int   g_offset[N_EXPERTS + 2];
__device__ int   g_cursor[N_EXPERTS];
__device__ int   g_tok_e0[TOK];
__device__ int   g_tok_e1[TOK];
__device__ float g_tok_p0[TOK];
__device__ float g_tok_p1[TOK];
__device__ float g_tok_om[TOK];
__device__ int   g_assign_tok[TOT_ROWS];
__device__ float g_assign_w[TOT_ROWS];

// ----------------------------- mma helpers ---------------------------------
__device__ __forceinline__ void mma16816(float d[4], const uint32_t a[4],
                                         uint32_t b0, uint32_t b1) {
    asm volatile(
        "mma.sync.aligned.m16n8k16.row.col.f32.bf16.bf16.f32 "
        "{%0,%1,%2,%3}, {%4,%5,%6,%7}, {%8,%9}, {%0,%1,%2,%3};"
        : "+f"(d[0]), "+f"(d[1]), "+f"(d[2]), "+f"(d[3])
        : "r"(a[0]), "r"(a[1]), "r"(a[2]), "r"(a[3]), "r"(b0), "r"(b1));
}

// split (x,y) fp32 pair into hi/lo bf16x2 packs (x in low half)
__device__ __forceinline__ void split2(float x, float y, uint32_t& hi, uint32_t& lo) {
    __nv_bfloat162 h = __floats2bfloat162_rn(x, y);
    hi = *(uint32_t*)&h;
    float rx = x - __bfloat162float(h.x);
    float ry = y - __bfloat162float(h.y);
    __nv_bfloat162 l = __floats2bfloat162_rn(rx, ry);
    lo = *(uint32_t*)&l;
}

// ----------------------------- init / zero ---------------------------------
__global__ void k_zero(float4* __restrict__ out4) {
    unsigned i = blockIdx.x * 256u + threadIdx.x;
    if (i < OUT_ELEMS / 4) out4[i] = make_float4(0.f, 0.f, 0.f, 0.f);
    if (blockIdx.x == 0 && threadIdx.x <= N_EXPERTS) g_count[threadIdx.x] = 0;
}

// ----------------------------- gating --------------------------------------
__global__ void k_gate(const float* __restrict__ x,
                       const int*   __restrict__ task_ids,
                       const float* __restrict__ temb,
                       const float* __restrict__ gw,
                       const float* __restrict__ gb,
                       float* __restrict__ out_logits) {
    const int t   = blockIdx.x;
    const int tid = threadIdx.x;
    const int task = task_ids[t / SEQ];
    const float* xr = x    + (size_t)t    * D_MODEL;
    const float* tr = temb + (size_t)task * D_MODEL;

    float acc[N_EXPERTS];
#pragma unroll
    for (int e = 0; e < N_EXPERTS; e++) acc[e] = 0.f;
    for (int d = tid; d < 2 * D_MODEL; d += 256) {
        float v = (d < D_MODEL) ? xr[d] : tr[d - D_MODEL];
        const float* g = gw + (size_t)d * N_EXPERTS;
#pragma unroll
        for (int e = 0; e < N_EXPERTS; e++) acc[e] += v * g[e];
    }
#pragma unroll
    for (int e = 0; e < N_EXPERTS; e++)
#pragma unroll
        for (int off = 16; off > 0; off >>= 1)
            acc[e] += __shfl_down_sync(0xffffffffu, acc[e], off);

    __shared__ float s_acc[8][N_EXPERTS];
    const int warp = tid >> 5, lane = tid & 31;
    if (lane == 0)
#pragma unroll
        for (int e = 0; e < N_EXPERTS; e++) s_acc[warp][e] = acc[e];
    __syncthreads();

    if (tid == 0) {
        float lg[N_EXPERTS];
#pragma unroll
        for (int e = 0; e < N_EXPERTS; e++) {
            float s = gb[e];
#pragma unroll
            for (int w = 0; w < 8; w++) s += s_acc[w][e];
            lg[e] = s;
            out_logits[(size_t)t * N_EXPERTS + e] = s;
        }
        int e0 = 0; float v0 = lg[0];
#pragma unroll
        for (int e = 1; e < N_EXPERTS; e++) if (lg[e] > v0) { v0 = lg[e]; e0 = e; }
        int e1 = -1; float v1 = -1e30f;
#pragma unroll
        for (int e = 0; e < N_EXPERTS; e++)
            if (e != e0 && lg[e] > v1) { v1 = lg[e]; e1 = e; }
        float ex = expf(v1 - v0);
        float p0 = 1.f / (1.f + ex);
        g_tok_e0[t] = e0;  g_tok_e1[t] = e1;
        g_tok_p0[t] = p0;  g_tok_p1[t] = ex / (1.f + ex);
        g_tok_om[t] = 1.f - p0;
        atomicAdd(&g_count[e0], 1);
        atomicAdd(&g_count[e1], 1);
    }
}

__global__ void k_scan() {
    if (blockIdx.x == 0 && threadIdx.x == 0) {
        int o = 0;
        for (int e = 0; e < N_EXPERTS; e++) { g_offset[e] = o; g_cursor[e] = o; o += g_count[e]; }
        g_offset[N_EXPERTS]     = o;
        g_offset[N_EXPERTS + 1] = o + TOK;
    }
}

// atomic placement (row order within an expert is irrelevant to values)
__global__ void k_place() {
    const int t = blockIdx.x * 256 + threadIdx.x;
    const int e0 = g_tok_e0[t], e1 = g_tok_e1[t];
    const int p0pos = atomicAdd(&g_cursor[e0], 1);
    g_assign_tok[p0pos] = t;  g_assign_w[p0pos] = g_tok_p0[t];
    const int p1pos = atomicAdd(&g_cursor[e1], 1);
    g_assign_tok[p1pos] = t;  g_assign_w[p1pos] = g_tok_p1[t];
    const int ub = g_offset[N_EXPERTS] + t;
    g_assign_tok[ub] = t;     g_assign_w[ub] = g_tok_om[t];
}

// ---------------------------------------------------------------------------
// MMA over one BK=16 chunk held as packed bf16x2 hi/lo in smem.
// 8 warps (2x4), warp tile 64x32; g = lane>>2 (row/col), c = lane&3 (k-pair).
// ---------------------------------------------------------------------------
__device__ __forceinline__ void mma_chunk(float d[4][4][4],
                                          const uint32_t* Ah, const uint32_t* Al,
                                          const uint32_t* Bh, const uint32_t* Bl,
                                          int wm, int wn, int g, int c) {
    uint32_t ah[4][4], al[4][4];
#pragma unroll
    for (int mt = 0; mt < 4; mt++) {
        const int r0 = (wm * 64 + mt * 16 + g) * ASTRIDE;
        const int r1 = r0 + 8 * ASTRIDE;
        ah[mt][0] = Ah[r0 + c];     al[mt][0] = Al[r0 + c];
        ah[mt][1] = Ah[r1 + c];     al[mt][1] = Al[r1 + c];
        ah[mt][2] = Ah[r0 + c + 4]; al[mt][2] = Al[r0 + c + 4];
        ah[mt][3] = Ah[r1 + c + 4]; al[mt][3] = Al[r1 + c + 4];
    }
    uint32_t bh[4][2], bl[4][2];
#pragma unroll
    for (int nt = 0; nt < 4; nt++) {
        const int n = wn * 32 + nt * 8 + g;
        bh[nt][0] = Bh[c * BSTRIDE + n];        bl[nt][0] = Bl[c * BSTRIDE + n];
        bh[nt][1] = Bh[(c + 4) * BSTRIDE + n];  bl[nt][1] = Bl[(c + 4) * BSTRIDE + n];
    }
#pragma unroll
    for (int mt = 0; mt < 4; mt++)
#pragma unroll
        for (int nt = 0; nt < 4; nt++) {
            mma16816(d[mt][nt], ah[mt], bh[nt][0], bh[nt][1]);
            mma16816(d[mt][nt], ah[mt], bl[nt][0], bl[nt][1]);
            mma16816(d[mt][nt], al[mt], bh[nt][0], bh[nt][1]);
        }
}

#define AWORDS (128 * ASTRIDE)   // 1536
#define BWORDS (8 * BSTRIDE)     // 1088

// ----------------------------- FFN1: H = gelu(X @ W1 + b1) -----------------
// grid (D_FF/128, 64, 9), 256 threads, 2-stage double buffer.
__global__ void __launch_bounds__(256)
k_ffn1(const float* __restrict__ x,
       const float* __restrict__ w1,  const float* __restrict__ b1,
       const float* __restrict__ uw1, const float* __restrict__ ub1) {
    const int z    = blockIdx.z;
    const int roff = g_offset[z];
    const int cnt  = g_offset[z + 1] - roff;
    const int m0   = blockIdx.y * 128;
    if (m0 >= cnt) return;
    const int f0   = blockIdx.x * 128;

    const float* __restrict__ W    = (z < N_EXPERTS) ? (w1 + (size_t)z * D_MODEL * D_FF) : uw1;
    const float* __restrict__ bias = (z < N_EXPERTS) ? (b1 + (size_t)z * D_FF) : ub1;

    __shared__ int      s_tok[128];
    __shared__ uint32_t As_h[2][AWORDS];
    __shared__ uint32_t As_l[2][AWORDS];
    __shared__ uint32_t Bs_h[2][BWORDS];
    __shared__ uint32_t Bs_l[2][BWORDS];

    const int tid  = threadIdx.x;
    const int wid  = tid >> 5;
    const int lane = tid & 31;
    const int wm = wid >> 2, wn = wid & 3;
    const int g = lane >> 2, c = lane & 3;

    if (tid < 128) {
        const int mm = m0 + tid;
        s_tok[tid] = g_assign_tok[roff + ((mm < cnt) ? mm : 0)];
    }
    __syncthreads();

    int   rA[4], kpA[4], kpB[4], fB[4];
    unsigned arow[4];
#pragma unroll
    for (int q = 0; q < 4; q++) {
        const int ia = tid + q * 256;
        rA[q]  = ia >> 3;  kpA[q] = ia & 7;
        arow[q] = (unsigned)s_tok[rA[q]] * (unsigned)D_MODEL;
        kpB[q] = ia >> 7;  fB[q]  = ia & 127;
    }

    float d[4][4][4];
#pragma unroll
    for (int a = 0; a < 4; a++)
#pragma unroll
        for (int b = 0; b < 4; b++)
#pragma unroll
            for (int e = 0; e < 4; e++) d[a][b][e] = 0.f;

    float2 pa[4];
    float  pb0[4], pb1[4];
#pragma unroll
    for (int q = 0; q < 4; q++) {
        pa[q]  = *(const float2*)(x + (size_t)arow[q] + 2 * kpA[q]);
        pb0[q] = W[(size_t)(2 * kpB[q])     * D_FF + f0 + fB[q]];
        pb1[q] = W[(size_t)(2 * kpB[q] + 1) * D_FF + f0 + fB[q]];
    }

    constexpr int NCH = D_MODEL / 16;   // 32
    for (int ch = 0; ch < NCH; ch++) {
        const int buf = ch & 1;
#pragma unroll
        for (int q = 0; q < 4; q++) {
            uint32_t h, l;
            split2(pa[q].x, pa[q].y, h, l);
            As_h[buf][rA[q] * ASTRIDE + kpA[q]] = h;
            As_l[buf][rA[q] * ASTRIDE + kpA[q]] = l;
            split2(pb0[q], pb1[q], h, l);
            Bs_h[buf][kpB[q] * BSTRIDE + fB[q]] = h;
            Bs_l[buf][kpB[q] * BSTRIDE + fB[q]] = l;
        }
        if (ch + 1 < NCH) {
            const int k0 = (ch + 1) * 16;
#pragma unroll
            for (int q = 0; q < 4; q++) {
                pa[q]  = *(const float2*)(x + (size_t)arow[q] + k0 + 2 * kpA[q]);
                pb0[q] = W[(size_t)(k0 + 2 * kpB[q])     * D_FF + f0 + fB[q]];
                pb1[q] = W[(size_t)(k0 + 2 * kpB[q] + 1) * D_FF + f0 + fB[q]];
            }
        }
        __syncthreads();
        mma_chunk(d, As_h[buf], As_l[buf], Bs_h[buf], Bs_l[buf], wm, wn, g, c);
    }

    // epilogue: bias + exact gelu -> packed hi/lo H
#pragma unroll
    for (int mt = 0; mt < 4; mt++)
#pragma unroll
        for (int half = 0; half < 2; half++) {
            const int m = wm * 64 + mt * 16 + g + half * 8;
            if (m0 + m >= cnt) continue;
            const size_t hbase = (size_t)(roff + m0 + m) * HKP;
#pragma unroll
            for (int nt = 0; nt < 4; nt++) {
                const int f = f0 + wn * 32 + nt * 8 + 2 * c;
                float v0 = d[mt][nt][half * 2 + 0] + bias[f];
                float v1 = d[mt][nt][half * 2 + 1] + bias[f + 1];
                v0 = 0.5f * v0 * (1.0f + erff(v0 * 0.70710678118654752f));
                v1 = 0.5f * v1 * (1.0f + erff(v1 * 0.70710678118654752f));
                uint32_t h, l;
                split2(v0, v1, h, l);
                g_Hh[hbase + (f >> 1)] = h;
                g_Hl[hbase + (f >> 1)] = l;
            }
        }
}

// ----------------------------- FFN2: out += w*(H @ W2 + b2) ----------------
// grid (D_MODEL/128, 64, 9), 2-stage double buffer, A staged without split.
__global__ void __launch_bounds__(256)
k_ffn2(float* __restrict__ out,
       const float* __restrict__ w2,  const float* __restrict__ b2,
       const float* __restrict__ uw2, const float* __restrict__ ub2) {
    const int z    = blockIdx.z;
    const int roff = g_offset[z];
    const int cnt  = g_offset[z + 1] - roff;
    const int m0   = blockIdx.y * 128;
    if (m0 >= cnt) return;
    const int d0   = blockIdx.x * 128;

    const float* __restrict__ W    = (z < N_EXPERTS) ? (w2 + (size_t)z * D_FF * D_MODEL) : uw2;
    const float* __restrict__ bias = (z < N_EXPERTS) ? (b2 + (size_t)z * D_MODEL) : ub2;

    __shared__ int      s_tok[128];
    __shared__ float    s_w[128];
    __shared__ uint32_t As_h[2][AWORDS];
    __shared__ uint32_t As_l[2][AWORDS];
    __shared__ uint32_t Bs_h[2][BWORDS];
    __shared__ uint32_t Bs_l[2][BWORDS];

    const int tid  = threadIdx.x;
    const int wid  = tid >> 5;
    const int lane = tid & 31;
    const int wm = wid >> 2, wn = wid & 3;
    const int g = lane >> 2, c = lane & 3;

    if (tid < 128) {
        const int mm = m0 + tid;
        const int rr = roff + ((mm < cnt) ? mm : 0);
        s_tok[tid] = g_assign_tok[rr];
        s_w[tid]   = g_assign_w[rr];
    }
    __syncthreads();

    int   rA[4], kpA[4], kpB[4], fB[4];
    size_t arowp[4];
#pragma unroll
    for (int q = 0; q < 4; q++) {
        const int ia = tid + q * 256;
        rA[q]  = ia >> 3;  kpA[q] = ia & 7;
        const int mm = m0 + rA[q];
        arowp[q] = (size_t)(roff + ((mm < cnt) ? mm : m0)) * HKP;
        kpB[q] = ia >> 7;  fB[q]  = ia & 127;
    }

    float d[4][4][4];
#pragma unroll
    for (int a = 0; a < 4; a++)
#pragma unroll
        for (int b = 0; b < 4; b++)
#pragma unroll
            for (int e = 0; e < 4; e++) d[a][b][e] = 0.f;

    uint32_t pah[4], pal[4];
    float    pb0[4], pb1[4];
#pragma unroll
    for (int q = 0; q < 4; q++) {
        pah[q] = g_Hh[arowp[q] + kpA[q]];
        pal[q] = g_Hl[arowp[q] + kpA[q]];
        pb0[q] = W[(size_t)(2 * kpB[q])     * D_MODEL + d0 + fB[q]];
        pb1[q] = W[(size_t)(2 * kpB[q] + 1) * D_MODEL + d0 + fB[q]];
    }

    constexpr int NCH = D_FF / 16;   // 128
    for (int ch = 0; ch < NCH; ch++) {
        const int buf = ch & 1;
#pragma unroll
        for (int q = 0; q < 4; q++) {
            As_h[buf][rA[q] * ASTRIDE + kpA[q]] = pah[q];
            As_l[buf][rA[q] * ASTRIDE + kpA[q]] = pal[q];
            uint32_t h, l;
            split2(pb0[q], pb1[q], h, l);
            Bs_h[buf][kpB[q] * BSTRIDE + fB[q]] = h;
            Bs_l[buf][kpB[q] * BSTRIDE + fB[q]] = l;
        }
        if (ch + 1 < NCH) {
            const int kp0 = (ch + 1) * 8;
            const int k0  = (ch + 1) * 16;
#pragma unroll
            for (int q = 0; q < 4; q++) {
                pah[q] = g_Hh[arowp[q] + kp0 + kpA[q]];
                pal[q] = g_Hl[arowp[q] + kp0 + kpA[q]];
                pb0[q] = W[(size_t)(k0 + 2 * kpB[q])     * D_MODEL + d0 + fB[q]];
                pb1[q] = W[(size_t)(k0 + 2 * kpB[q] + 1) * D_MODEL + d0 + fB[q]];
            }
        }
        __syncthreads();
        mma_chunk(d, As_h[buf], As_l[buf], Bs_h[buf], Bs_l[buf], wm, wn, g, c);
    }

    // epilogue: weighted atomic accumulation
#pragma unroll
    for (int mt = 0; mt < 4; mt++)
#pragma unroll
        for (int half = 0; half < 2; half++) {
            const int m = wm * 64 + mt * 16 + g + half * 8;
            if (m0 + m >= cnt) continue;
            const int   tok = s_tok[m];
            const float wr  = s_w[m];
            float* orow = out + (size_t)tok * D_MODEL;
#pragma unroll
            for (int nt = 0; nt < 4; nt++) {
                const int dd = d0 + wn * 32 + nt * 8 + 2 * c;
                atomicAdd(&orow[dd],     wr * (d[mt][nt][half * 2 + 0] + bias[dd]));
                atomicAdd(&orow[dd + 1], wr * (d[mt][nt][half * 2 + 1] + bias[dd + 1]));
            }
        }
}

// ----------------------------- launch --------------------------------------
extern "C" void kernel_launch(void* const* d_in, const int* in_sizes, int n_in,
                              void* d_out, int out_size) {
    const float* x        = (const float*)d_in[0];
    const int*   task_ids = (const int*)  d_in[1];
    const float* temb     = (const float*)d_in[2];
    const float* gw       = (const float*)d_in[3];
    const float* gb       = (const float*)d_in[4];
    const float* w1       = (const float*)d_in[5];
    const float* b1       = (const float*)d_in[6];
    const float* w2       = (const float*)d_in[7];
    const float* b2       = (const float*)d_in[8];
    const float* uw1      = (const float*)d_in[9];
    const float* ub1      = (const float*)d_in[10];
    const float* uw2      = (const float*)d_in[11];
    const float* ub2      = (const float*)d_in[12];

    float* out        = (float*)d_out;
    float* out_logits = out + OUT_ELEMS;

    k_zero<<<OUT_ELEMS / 4 / 256, 256>>>((float4*)out);
    k_gate<<<TOK, 256>>>(x, task_ids, temb, gw, gb, out_logits);
    k_scan<<<1, 32>>>();
    k_place<<<TOK / 256, 256>>>();
    k_ffn1<<<dim3(D_FF / 128, TOK / 128, NGRP), 256>>>(x, w1, b1, uw1, ub1);
    k_ffn2<<<dim3(D_MODEL / 128, TOK / 128, NGRP), 256>>>(out, w2, b2, uw2, ub2);
}

// round 8
// speedup vs baseline: 3.6420x; 1.2222x over previous
#include <cuda_runtime.h>
#include <cuda_fp16.h>
#include <math.h>
#include <stdint.h>

// ---------------------------------------------------------------------------
// TaskAwareMoE round 8: fp16 2-term emulated-fp32 mma.sync grouped GEMMs.
//   A*B ~= (Ah + Al) * Bh ; dropped term a*bl ~ 2^-11 relative (model: ~4e-4
//   total rel_err across both GEMMs, validated on the bf16 3-term case).
// ---------------------------------------------------------------------------

#define D_MODEL   512
#define D_FF      2048
#define N_EXPERTS 8
#define BATCH     8
#define SEQ       1024
#define TOK       (BATCH * SEQ)            // 8192
#define EXP_ROWS  (2 * TOK)                // 16384
#define TOT_ROWS  (EXP_ROWS + TOK)         // 24576
#define OUT_ELEMS (TOK * D_MODEL)          // 4,194,304
#define NGRP      (N_EXPERTS + 1)
#define HKP       (D_FF / 2)               // 1024 k-pairs per H row

#define ASTRIDE 12      // uint32 words per A row  (8 used + 4 pad) -> bank-free
#define BSTRIDE 136     // uint32 words per B k-pair row (128 used + 8 pad)

// ----------------------------- static scratch ------------------------------
__device__ uint32_t g_Hh[(size_t)TOT_ROWS * HKP];  // packed fp16x2 hi pairs
__device__ uint32_t g_Hl[(size_t)TOT_ROWS * HKP];  // packed fp16x2 lo pairs
__device__ int   g_count[N_EXPERTS + 1];
__device__ int   g_offset[N_EXPERTS + 2];
__device__ int   g_cursor[N_EXPERTS];
__device__ int   g_tok_e0[TOK];
__device__ int   g_tok_e1[TOK];
__device__ float g_tok_p0[TOK];
__device__ float g_tok_p1[TOK];
__device__ float g_tok_om[TOK];
__device__ int   g_assign_tok[TOT_ROWS];
__device__ float g_assign_w[TOT_ROWS];

// ----------------------------- mma helpers ---------------------------------
__device__ __forceinline__ void mma16816(float d[4], const uint32_t a[4],
                                         uint32_t b0, uint32_t b1) {
    asm volatile(
        "mma.sync.aligned.m16n8k16.row.col.f32.f16.f16.f32 "
        "{%0,%1,%2,%3}, {%4,%5,%6,%7}, {%8,%9}, {%0,%1,%2,%3};"
        : "+f"(d[0]), "+f"(d[1]), "+f"(d[2]), "+f"(d[3])
        : "r"(a[0]), "r"(a[1]), "r"(a[2]), "r"(a[3]), "r"(b0), "r"(b1));
}

// split (x,y) fp32 pair into hi/lo fp16x2 packs (x in low half)
__device__ __forceinline__ void split2h(float x, float y, uint32_t& hi, uint32_t& lo) {
    __half2 h = __floats2half2_rn(x, y);
    hi = *(uint32_t*)&h;
    float rx = x - __half2float(__low2half(h));
    float ry = y - __half2float(__high2half(h));
    __half2 l = __floats2half2_rn(rx, ry);
    lo = *(uint32_t*)&l;
}
__device__ __forceinline__ uint32_t pack2h(float x, float y) {
    __half2 h = __floats2half2_rn(x, y);
    return *(uint32_t*)&h;
}

// ----------------------------- init / zero ---------------------------------
__global__ void k_zero(float4* __restrict__ out4) {
    unsigned i = blockIdx.x * 256u + threadIdx.x;
    if (i < OUT_ELEMS / 4) out4[i] = make_float4(0.f, 0.f, 0.f, 0.f);
    if (blockIdx.x == 0 && threadIdx.x <= N_EXPERTS) g_count[threadIdx.x] = 0;
}

// ----------------------------- gating --------------------------------------
__global__ void k_gate(const float* __restrict__ x,
                       const int*   __restrict__ task_ids,
                       const float* __restrict__ temb,
                       const float* __restrict__ gw,
                       const float* __restrict__ gb,
                       float* __restrict__ out_logits) {
    const int t   = blockIdx.x;
    const int tid = threadIdx.x;
    const int task = task_ids[t / SEQ];
    const float* xr = x    + (size_t)t    * D_MODEL;
    const float* tr = temb + (size_t)task * D_MODEL;

    float acc[N_EXPERTS];
#pragma unroll
    for (int e = 0; e < N_EXPERTS; e++) acc[e] = 0.f;
    for (int d = tid; d < 2 * D_MODEL; d += 256) {
        float v = (d < D_MODEL) ? xr[d] : tr[d - D_MODEL];
        const float* g = gw + (size_t)d * N_EXPERTS;
#pragma unroll
        for (int e = 0; e < N_EXPERTS; e++) acc[e] += v * g[e];
    }
#pragma unroll
    for (int e = 0; e < N_EXPERTS; e++)
#pragma unroll
        for (int off = 16; off > 0; off >>= 1)
            acc[e] += __shfl_down_sync(0xffffffffu, acc[e], off);

    __shared__ float s_acc[8][N_EXPERTS];
    const int warp = tid >> 5, lane = tid & 31;
    if (lane == 0)
#pragma unroll
        for (int e = 0; e < N_EXPERTS; e++) s_acc[warp][e] = acc[e];
    __syncthreads();

    if (tid == 0) {
        float lg[N_EXPERTS];
#pragma unroll
        for (int e = 0; e < N_EXPERTS; e++) {
            float s = gb[e];
#pragma unroll
            for (int w = 0; w < 8; w++) s += s_acc[w][e];
            lg[e] = s;
            out_logits[(size_t)t * N_EXPERTS + e] = s;
        }
        int e0 = 0; float v0 = lg[0];
#pragma unroll
        for (int e = 1; e < N_EXPERTS; e++) if (lg[e] > v0) { v0 = lg[e]; e0 = e; }
        int e1 = -1; float v1 = -1e30f;
#pragma unroll
        for (int e = 0; e < N_EXPERTS; e++)
            if (e != e0 && lg[e] > v1) { v1 = lg[e]; e1 = e; }
        float ex = expf(v1 - v0);
        float p0 = 1.f / (1.f + ex);
        g_tok_e0[t] = e0;  g_tok_e1[t] = e1;
        g_tok_p0[t] = p0;  g_tok_p1[t] = ex / (1.f + ex);
        g_tok_om[t] = 1.f - p0;
        atomicAdd(&g_count[e0], 1);
        atomicAdd(&g_count[e1], 1);
    }
}

__global__ void k_scan() {
    if (blockIdx.x == 0 && threadIdx.x == 0) {
        int o = 0;
        for (int e = 0; e < N_EXPERTS; e++) { g_offset[e] = o; g_cursor[e] = o; o += g_count[e]; }
        g_offset[N_EXPERTS]     = o;
        g_offset[N_EXPERTS + 1] = o + TOK;
    }
}

// atomic placement (row order within an expert is irrelevant to values)
__global__ void k_place() {
    const int t = blockIdx.x * 256 + threadIdx.x;
    const int e0 = g_tok_e0[t], e1 = g_tok_e1[t];
    const int p0pos = atomicAdd(&g_cursor[e0], 1);
    g_assign_tok[p0pos] = t;  g_assign_w[p0pos] = g_tok_p0[t];
    const int p1pos = atomicAdd(&g_cursor[e1], 1);
    g_assign_tok[p1pos] = t;  g_assign_w[p1pos] = g_tok_p1[t];
    const int ub = g_offset[N_EXPERTS] + t;
    g_assign_tok[ub] = t;     g_assign_w[ub] = g_tok_om[t];
}

// ---------------------------------------------------------------------------
// MMA over one BK=16 chunk: A as fp16 hi/lo, B as fp16 hi only. 2 terms.
// 8 warps (2x4), warp tile 64x32; g = lane>>2 (row/col), c = lane&3 (k-pair).
// ---------------------------------------------------------------------------
__device__ __forceinline__ void mma_chunk(float d[4][4][4],
                                          const uint32_t* Ah, const uint32_t* Al,
                                          const uint32_t* Bh,
                                          int wm, int wn, int g, int c) {
    uint32_t ah[4][4], al[4][4];
#pragma unroll
    for (int mt = 0; mt < 4; mt++) {
        const int r0 = (wm * 64 + mt * 16 + g) * ASTRIDE;
        const int r1 = r0 + 8 * ASTRIDE;
        ah[mt][0] = Ah[r0 + c];     al[mt][0] = Al[r0 + c];
        ah[mt][1] = Ah[r1 + c];     al[mt][1] = Al[r1 + c];
        ah[mt][2] = Ah[r0 + c + 4]; al[mt][2] = Al[r0 + c + 4];
        ah[mt][3] = Ah[r1 + c + 4]; al[mt][3] = Al[r1 + c + 4];
    }
    uint32_t bh[4][2];
#pragma unroll
    for (int nt = 0; nt < 4; nt++) {
        const int n = wn * 32 + nt * 8 + g;
        bh[nt][0] = Bh[c * BSTRIDE + n];
        bh[nt][1] = Bh[(c + 4) * BSTRIDE + n];
    }
#pragma unroll
    for (int mt = 0; mt < 4; mt++)
#pragma unroll
        for (int nt = 0; nt < 4; nt++) {
            mma16816(d[mt][nt], ah[mt], bh[nt][0], bh[nt][1]);
            mma16816(d[mt][nt], al[mt], bh[nt][0], bh[nt][1]);
        }
}

#define AWORDS (128 * ASTRIDE)   // 1536
#define BWORDS (8 * BSTRIDE)     // 1088

// ----------------------------- FFN1: H = gelu(X @ W1 + b1) -----------------
// grid (D_FF/128, 64, 9), 256 threads, 2-stage double buffer.
__global__ void __launch_bounds__(256)
k_ffn1(const float* __restrict__ x,
       const float* __restrict__ w1,  const float* __restrict__ b1,
       const float* __restrict__ uw1, const float* __restrict__ ub1) {
    const int z    = blockIdx.z;
    const int roff = g_offset[z];
    const int cnt  = g_offset[z + 1] - roff;
    const int m0   = blockIdx.y * 128;
    if (m0 >= cnt) return;
    const int f0   = blockIdx.x * 128;

    const float* __restrict__ W    = (z < N_EXPERTS) ? (w1 + (size_t)z * D_MODEL * D_FF) : uw1;
    const float* __restrict__ bias = (z < N_EXPERTS) ? (b1 + (size_t)z * D_FF) : ub1;

    __shared__ int      s_tok[128];
    __shared__ uint32_t As_h[2][AWORDS];
    __shared__ uint32_t As_l[2][AWORDS];
    __shared__ uint32_t Bs_h[2][BWORDS];

    const int tid  = threadIdx.x;
    const int wid  = tid >> 5;
    const int lane = tid & 31;
    const int wm = wid >> 2, wn = wid & 3;
    const int g = lane >> 2, c = lane & 3;

    if (tid < 128) {
        const int mm = m0 + tid;
        s_tok[tid] = g_assign_tok[roff + ((mm < cnt) ? mm : 0)];
    }
    __syncthreads();

    int   rA[4], kpA[4], kpB[4], fB[4];
    unsigned arow[4];
#pragma unroll
    for (int q = 0; q < 4; q++) {
        const int ia = tid + q * 256;
        rA[q]  = ia >> 3;  kpA[q] = ia & 7;
        arow[q] = (unsigned)s_tok[rA[q]] * (unsigned)D_MODEL;
        kpB[q] = ia >> 7;  fB[q]  = ia & 127;
    }

    float d[4][4][4];
#pragma unroll
    for (int a = 0; a < 4; a++)
#pragma unroll
        for (int b = 0; b < 4; b++)
#pragma unroll
            for (int e = 0; e < 4; e++) d[a][b][e] = 0.f;

    float2 pa[4];
    float  pb0[4], pb1[4];
#pragma unroll
    for (int q = 0; q < 4; q++) {
        pa[q]  = *(const float2*)(x + (size_t)arow[q] + 2 * kpA[q]);
        pb0[q] = W[(size_t)(2 * kpB[q])     * D_FF + f0 + fB[q]];
        pb1[q] = W[(size_t)(2 * kpB[q] + 1) * D_FF + f0 + fB[q]];
    }

    constexpr int NCH = D_MODEL / 16;   // 32
    for (int ch = 0; ch < NCH; ch++) {
        const int buf = ch & 1;
#pragma unroll
        for (int q = 0; q < 4; q++) {
            uint32_t h, l;
            split2h(pa[q].x, pa[q].y, h, l);
            As_h[buf][rA[q] * ASTRIDE + kpA[q]] = h;
            As_l[buf][rA[q] * ASTRIDE + kpA[q]] = l;
            Bs_h[buf][kpB[q] * BSTRIDE + fB[q]] = pack2h(pb0[q], pb1[q]);
        }
        if (ch + 1 < NCH) {
            const int k0 = (ch + 1) * 16;
#pragma unroll
            for (int q = 0; q < 4; q++) {
                pa[q]  = *(const float2*)(x + (size_t)arow[q] + k0 + 2 * kpA[q]);
                pb0[q] = W[(size_t)(k0 + 2 * kpB[q])     * D_FF + f0 + fB[q]];
                pb1[q] = W[(size_t)(k0 + 2 * kpB[q] + 1) * D_FF + f0 + fB[q]];
            }
        }
        __syncthreads();
        mma_chunk(d, As_h[buf], As_l[buf], Bs_h[buf], wm, wn, g, c);
    }

    // epilogue: bias + exact gelu -> packed fp16 hi/lo H
#pragma unroll
    for (int mt = 0; mt < 4; mt++)
#pragma unroll
        for (int half = 0; half < 2; half++) {
            const int m = wm * 64 + mt * 16 + g + half * 8;
            if (m0 + m >= cnt) continue;
            const size_t hbase = (size_t)(roff + m0 + m) * HKP;
#pragma unroll
            for (int nt = 0; nt < 4; nt++) {
                const int f = f0 + wn * 32 + nt * 8 + 2 * c;
                float v0 = d[mt][nt][half * 2 + 0] + bias[f];
                float v1 = d[mt][nt][half * 2 + 1] + bias[f + 1];
                v0 = 0.5f * v0 * (1.0f + erff(v0 * 0.70710678118654752f));
                v1 = 0.5f * v1 * (1.0f + erff(v1 * 0.70710678118654752f));
                uint32_t h, l;
                split2h(v0, v1, h, l);
                g_Hh[hbase + (f >> 1)] = h;
                g_Hl[hbase + (f >> 1)] = l;
            }
        }
}

// ----------------------------- FFN2: out += w*(H @ W2 + b2) ----------------
// grid (D_MODEL/128, 64, 9), 2-stage double buffer, A staged without split.
__global__ void __launch_bounds__(256)
k_ffn2(float* __restrict__ out,
       const float* __restrict__ w2,  const float* __restrict__ b2,
       const float* __restrict__ uw2, const float* __restrict__ ub2) {
    const int z    = blockIdx.z;
    const int roff = g_offset[z];
    const int cnt  = g_offset[z + 1] - roff;
    const int m0   = blockIdx.y * 128;
    if (m0 >= cnt) return;
    const int d0   = blockIdx.x * 128;

    const float* __restrict__ W    = (z < N_EXPERTS) ? (w2 + (size_t)z * D_FF * D_MODEL) : uw2;
    const float* __restrict__ bias = (z < N_EXPERTS) ? (b2 + (size_t)z * D_MODEL) : ub2;

    __shared__ int      s_tok[128];
    __shared__ float    s_w[128];
    __shared__ uint32_t As_h[2][AWORDS];
    __shared__ uint32_t As_l[2][AWORDS];
    __shared__ uint32_t Bs_h[2][BWORDS];

    const int tid  = threadIdx.x;
    const int wid  = tid >> 5;
    const int lane = tid & 31;
    const int wm = wid >> 2, wn = wid & 3;
    const int g = lane >> 2, c = lane & 3;

    if (tid < 128) {
        const int mm = m0 + tid;
        const int rr = roff + ((mm < cnt) ? mm : 0);
        s_tok[tid] = g_assign_tok[rr];
        s_w[tid]   = g_assign_w[rr];
    }
    __syncthreads();

    int   rA[4], kpA[4], kpB[4], fB[4];
    size_t arowp[4];
#pragma unroll
    for (int q = 0; q < 4; q++) {
        const int ia = tid + q * 256;
        rA[q]  = ia >> 3;  kpA[q] = ia & 7;
        const int mm = m0 + rA[q];
        arowp[q] = (size_t)(roff + ((mm < cnt) ? mm : m0)) * HKP;
        kpB[q] = ia >> 7;  fB[q]  = ia & 127;
    }

    float d[4][4][4];
#pragma unroll
    for (int a = 0; a < 4; a++)
#pragma unroll
        for (int b = 0; b < 4; b++)
#pragma unroll
            for (int e = 0; e < 4; e++) d[a][b][e] = 0.f;

    uint32_t pah[4], pal[4];
    float    pb0[4], pb1[4];
#pragma unroll
    for (int q = 0; q < 4; q++) {
        pah[q] = g_Hh[arowp[q] + kpA[q]];
        pal[q] = g_Hl[arowp[q] + kpA[q]];
        pb0[q] = W[(size_t)(2 * kpB[q])     * D_MODEL + d0 + fB[q]];
        pb1[q] = W[(size_t)(2 * kpB[q] + 1) * D_MODEL + d0 + fB[q]];
    }

    constexpr int NCH = D_FF / 16;   // 128
    for (int ch = 0; ch < NCH; ch++) {
        const int buf = ch & 1;
#pragma unroll
        for (int q = 0; q < 4; q++) {
            As_h[buf][rA[q] * ASTRIDE + kpA[q]] = pah[q];
            As_l[buf][rA[q] * ASTRIDE + kpA[q]] = pal[q];
            Bs_h[buf][kpB[q] * BSTRIDE + fB[q]] = pack2h(pb0[q], pb1[q]);
        }
        if (ch + 1 < NCH) {
            const int kp0 = (ch + 1) * 8;
            const int k0  = (ch + 1) * 16;
#pragma unroll
            for (int q = 0; q < 4; q++) {
                pah[q] = g_Hh[arowp[q] + kp0 + kpA[q]];
                pal[q] = g_Hl[arowp[q] + kp0 + kpA[q]];
                pb0[q] = W[(size_t)(k0 + 2 * kpB[q])     * D_MODEL + d0 + fB[q]];
                pb1[q] = W[(size_t)(k0 + 2 * kpB[q] + 1) * D_MODEL + d0 + fB[q]];
            }
        }
        __syncthreads();
        mma_chunk(d, As_h[buf], As_l[buf], Bs_h[buf], wm, wn, g, c);
    }

    // epilogue: weighted atomic accumulation
#pragma unroll
    for (int mt = 0; mt < 4; mt++)
#pragma unroll
        for (int half = 0; half < 2; half++) {
            const int m = wm * 64 + mt * 16 + g + half * 8;
            if (m0 + m >= cnt) continue;
            const int   tok = s_tok[m];
            const float wr  = s_w[m];
            float* orow = out + (size_t)tok * D_MODEL;
#pragma unroll
            for (int nt = 0; nt < 4; nt++) {
                const int dd = d0 + wn * 32 + nt * 8 + 2 * c;
                atomicAdd(&orow[dd],     wr * (d[mt][nt][half * 2 + 0] + bias[dd]));
                atomicAdd(&orow[dd + 1], wr * (d[mt][nt][half * 2 + 1] + bias[dd + 1]));
            }
        }
}

// ----------------------------- launch --------------------------------------
extern "C" void kernel_launch(void* const* d_in, const int* in_sizes, int n_in,
                              void* d_out, int out_size) {
    const float* x        = (const float*)d_in[0];
    const int*   task_ids = (const int*)  d_in[1];
    const float* temb     = (const float*)d_in[2];
    const float* gw       = (const float*)d_in[3];
    const float* gb       = (const float*)d_in[4];
    const float* w1       = (const float*)d_in[5];
    const float* b1       = (const float*)d_in[6];
    const float* w2       = (const float*)d_in[7];
    const float* b2       = (const float*)d_in[8];
    const float* uw1      = (const float*)d_in[9];
    const float* ub1      = (const float*)d_in[10];
    const float* uw2      = (const float*)d_in[11];
    const float* ub2      = (const float*)d_in[12];

    float* out        = (float*)d_out;
    float* out_logits = out + OUT_ELEMS;

    k_zero<<<OUT_ELEMS / 4 / 256, 256>>>((float4*)out);
    k_gate<<<TOK, 256>>>(x, task_ids, temb, gw, gb, out_logits);
    k_scan<<<1, 32>>>();
    k_place<<<TOK / 256, 256>>>();
    k_ffn1<<<dim3(D_FF / 128, TOK / 128, NGRP), 256>>>(x, w1, b1, uw1, ub1);
    k_ffn2<<<dim3(D_MODEL / 128, TOK / 128, NGRP), 256>>>(out, w2, b2, uw2, ub2);
}

// round 9
// speedup vs baseline: 5.6687x; 1.5565x over previous
#include <cuda_runtime.h>
#include <cuda_fp16.h>
#include <math.h>
#include <stdint.h>

// ---------------------------------------------------------------------------
// TaskAwareMoE round 9: plain fp16 mma.sync grouped GEMMs (fp32 accumulate).
//   A,B rounded to fp16; 4 independent rounding sources -> predicted ~4.2e-4
//   rel_err (validated model). 16 HMMA per warp-chunk.
// ---------------------------------------------------------------------------

#define D_MODEL   512
#define D_FF      2048
#define N_EXPERTS 8
#define BATCH     8
#define SEQ       1024
#define TOK       (BATCH * SEQ)            // 8192
#define EXP_ROWS  (2 * TOK)                // 16384
#define TOT_ROWS  (EXP_ROWS + TOK)         // 24576
#define OUT_ELEMS (TOK * D_MODEL)          // 4,194,304
#define NGRP      (N_EXPERTS + 1)
#define HKP       (D_FF / 2)               // 1024 fp16x2 pairs per H row

#define ASTRIDE 12      // uint32 words per A row  (8 used + 4 pad) -> bank-free
#define BSTRIDE 136     // uint32 words per B k-pair row (128 used + 8 pad)

// ----------------------------- static scratch ------------------------------
__device__ uint32_t g_Hh[(size_t)TOT_ROWS * HKP];  // packed fp16x2 H
__device__ int   g_count[N_EXPERTS + 1];
__device__ int   g_offset[N_EXPERTS + 2];
__device__ int   g_cursor[N_EXPERTS];
__device__ int   g_tok_e0[TOK];
__device__ int   g_tok_e1[TOK];
__device__ float g_tok_p0[TOK];
__device__ float g_tok_p1[TOK];
__device__ float g_tok_om[TOK];
__device__ int   g_assign_tok[TOT_ROWS];
__device__ float g_assign_w[TOT_ROWS];

// ----------------------------- mma helpers ---------------------------------
__device__ __forceinline__ void mma16816(float d[4], const uint32_t a[4],
                                         uint32_t b0, uint32_t b1) {
    asm volatile(
        "mma.sync.aligned.m16n8k16.row.col.f32.f16.f16.f32 "
        "{%0,%1,%2,%3}, {%4,%5,%6,%7}, {%8,%9}, {%0,%1,%2,%3};"
        : "+f"(d[0]), "+f"(d[1]), "+f"(d[2]), "+f"(d[3])
        : "r"(a[0]), "r"(a[1]), "r"(a[2]), "r"(a[3]), "r"(b0), "r"(b1));
}
__device__ __forceinline__ uint32_t pack2h(float x, float y) {
    __half2 h = __floats2half2_rn(x, y);
    return *(uint32_t*)&h;
}

// ----------------------------- init / zero ---------------------------------
__global__ void k_zero(float4* __restrict__ out4) {
    unsigned i = blockIdx.x * 256u + threadIdx.x;
    if (i < OUT_ELEMS / 4) out4[i] = make_float4(0.f, 0.f, 0.f, 0.f);
    if (blockIdx.x == 0 && threadIdx.x <= N_EXPERTS) g_count[threadIdx.x] = 0;
}

// ----------------------------- gating --------------------------------------
__global__ void k_gate(const float* __restrict__ x,
                       const int*   __restrict__ task_ids,
                       const float* __restrict__ temb,
                       const float* __restrict__ gw,
                       const float* __restrict__ gb,
                       float* __restrict__ out_logits) {
    const int t   = blockIdx.x;
    const int tid = threadIdx.x;
    const int task = task_ids[t / SEQ];
    const float* xr = x    + (size_t)t    * D_MODEL;
    const float* tr = temb + (size_t)task * D_MODEL;

    float acc[N_EXPERTS];
#pragma unroll
    for (int e = 0; e < N_EXPERTS; e++) acc[e] = 0.f;
    for (int d = tid; d < 2 * D_MODEL; d += 256) {
        float v = (d < D_MODEL) ? xr[d] : tr[d - D_MODEL];
        const float* g = gw + (size_t)d * N_EXPERTS;
#pragma unroll
        for (int e = 0; e < N_EXPERTS; e++) acc[e] += v * g[e];
    }
#pragma unroll
    for (int e = 0; e < N_EXPERTS; e++)
#pragma unroll
        for (int off = 16; off > 0; off >>= 1)
            acc[e] += __shfl_down_sync(0xffffffffu, acc[e], off);

    __shared__ float s_acc[8][N_EXPERTS];
    const int warp = tid >> 5, lane = tid & 31;
    if (lane == 0)
#pragma unroll
        for (int e = 0; e < N_EXPERTS; e++) s_acc[warp][e] = acc[e];
    __syncthreads();

    if (tid == 0) {
        float lg[N_EXPERTS];
#pragma unroll
        for (int e = 0; e < N_EXPERTS; e++) {
            float s = gb[e];
#pragma unroll
            for (int w = 0; w < 8; w++) s += s_acc[w][e];
            lg[e] = s;
            out_logits[(size_t)t * N_EXPERTS + e] = s;
        }
        int e0 = 0; float v0 = lg[0];
#pragma unroll
        for (int e = 1; e < N_EXPERTS; e++) if (lg[e] > v0) { v0 = lg[e]; e0 = e; }
        int e1 = -1; float v1 = -1e30f;
#pragma unroll
        for (int e = 0; e < N_EXPERTS; e++)
            if (e != e0 && lg[e] > v1) { v1 = lg[e]; e1 = e; }
        float ex = expf(v1 - v0);
        float p0 = 1.f / (1.f + ex);
        g_tok_e0[t] = e0;  g_tok_e1[t] = e1;
        g_tok_p0[t] = p0;  g_tok_p1[t] = ex / (1.f + ex);
        g_tok_om[t] = 1.f - p0;
        atomicAdd(&g_count[e0], 1);
        atomicAdd(&g_count[e1], 1);
    }
}

__global__ void k_scan() {
    if (blockIdx.x == 0 && threadIdx.x == 0) {
        int o = 0;
        for (int e = 0; e < N_EXPERTS; e++) { g_offset[e] = o; g_cursor[e] = o; o += g_count[e]; }
        g_offset[N_EXPERTS]     = o;
        g_offset[N_EXPERTS + 1] = o + TOK;
    }
}

// atomic placement (row order within an expert is irrelevant to values)
__global__ void k_place() {
    const int t = blockIdx.x * 256 + threadIdx.x;
    const int e0 = g_tok_e0[t], e1 = g_tok_e1[t];
    const int p0pos = atomicAdd(&g_cursor[e0], 1);
    g_assign_tok[p0pos] = t;  g_assign_w[p0pos] = g_tok_p0[t];
    const int p1pos = atomicAdd(&g_cursor[e1], 1);
    g_assign_tok[p1pos] = t;  g_assign_w[p1pos] = g_tok_p1[t];
    const int ub = g_offset[N_EXPERTS] + t;
    g_assign_tok[ub] = t;     g_assign_w[ub] = g_tok_om[t];
}

// ---------------------------------------------------------------------------
// MMA over one BK=16 chunk: plain fp16 A and B.
// 8 warps (2x4), warp tile 64x32; g = lane>>2 (row/col), c = lane&3 (k-pair).
// ---------------------------------------------------------------------------
__device__ __forceinline__ void mma_chunk(float d[4][4][4],
                                          const uint32_t* Ah, const uint32_t* Bh,
                                          int wm, int wn, int g, int c) {
    uint32_t ah[4][4];
#pragma unroll
    for (int mt = 0; mt < 4; mt++) {
        const int r0 = (wm * 64 + mt * 16 + g) * ASTRIDE;
        const int r1 = r0 + 8 * ASTRIDE;
        ah[mt][0] = Ah[r0 + c];
        ah[mt][1] = Ah[r1 + c];
        ah[mt][2] = Ah[r0 + c + 4];
        ah[mt][3] = Ah[r1 + c + 4];
    }
    uint32_t bh[4][2];
#pragma unroll
    for (int nt = 0; nt < 4; nt++) {
        const int n = wn * 32 + nt * 8 + g;
        bh[nt][0] = Bh[c * BSTRIDE + n];
        bh[nt][1] = Bh[(c + 4) * BSTRIDE + n];
    }
#pragma unroll
    for (int mt = 0; mt < 4; mt++)
#pragma unroll
        for (int nt = 0; nt < 4; nt++)
            mma16816(d[mt][nt], ah[mt], bh[nt][0], bh[nt][1]);
}

#define AWORDS (128 * ASTRIDE)   // 1536
#define BWORDS (8 * BSTRIDE)     // 1088

// ----------------------------- FFN1: H = gelu(X @ W1 + b1) -----------------
// grid (D_FF/128, 64, 9), 256 threads, 2-stage double buffer.
__global__ void __launch_bounds__(256)
k_ffn1(const float* __restrict__ x,
       const float* __restrict__ w1,  const float* __restrict__ b1,
       const float* __restrict__ uw1, const float* __restrict__ ub1) {
    const int z    = blockIdx.z;
    const int roff = g_offset[z];
    const int cnt  = g_offset[z + 1] - roff;
    const int m0   = blockIdx.y * 128;
    if (m0 >= cnt) return;
    const int f0   = blockIdx.x * 128;

    const float* __restrict__ W    = (z < N_EXPERTS) ? (w1 + (size_t)z * D_MODEL * D_FF) : uw1;
    const float* __restrict__ bias = (z < N_EXPERTS) ? (b1 + (size_t)z * D_FF) : ub1;

    __shared__ int      s_tok[128];
    __shared__ uint32_t As_h[2][AWORDS];
    __shared__ uint32_t Bs_h[2][BWORDS];

    const int tid  = threadIdx.x;
    const int wid  = tid >> 5;
    const int lane = tid & 31;
    const int wm = wid >> 2, wn = wid & 3;
    const int g = lane >> 2, c = lane & 3;

    if (tid < 128) {
        const int mm = m0 + tid;
        s_tok[tid] = g_assign_tok[roff + ((mm < cnt) ? mm : 0)];
    }
    __syncthreads();

    int   rA[4], kpA[4], kpB[4], fB[4];
    unsigned arow[4];
#pragma unroll
    for (int q = 0; q < 4; q++) {
        const int ia = tid + q * 256;
        rA[q]  = ia >> 3;  kpA[q] = ia & 7;
        arow[q] = (unsigned)s_tok[rA[q]] * (unsigned)D_MODEL;
        kpB[q] = ia >> 7;  fB[q]  = ia & 127;
    }

    float d[4][4][4];
#pragma unroll
    for (int a = 0; a < 4; a++)
#pragma unroll
        for (int b = 0; b < 4; b++)
#pragma unroll
            for (int e = 0; e < 4; e++) d[a][b][e] = 0.f;

    float2 pa[4];
    float  pb0[4], pb1[4];
#pragma unroll
    for (int q = 0; q < 4; q++) {
        pa[q]  = *(const float2*)(x + (size_t)arow[q] + 2 * kpA[q]);
        pb0[q] = W[(size_t)(2 * kpB[q])     * D_FF + f0 + fB[q]];
        pb1[q] = W[(size_t)(2 * kpB[q] + 1) * D_FF + f0 + fB[q]];
    }

    constexpr int NCH = D_MODEL / 16;   // 32
    for (int ch = 0; ch < NCH; ch++) {
        const int buf = ch & 1;
#pragma unroll
        for (int q = 0; q < 4; q++) {
            As_h[buf][rA[q] * ASTRIDE + kpA[q]] = pack2h(pa[q].x, pa[q].y);
            Bs_h[buf][kpB[q] * BSTRIDE + fB[q]] = pack2h(pb0[q], pb1[q]);
        }
        if (ch + 1 < NCH) {
            const int k0 = (ch + 1) * 16;
#pragma unroll
            for (int q = 0; q < 4; q++) {
                pa[q]  = *(const float2*)(x + (size_t)arow[q] + k0 + 2 * kpA[q]);
                pb0[q] = W[(size_t)(k0 + 2 * kpB[q])     * D_FF + f0 + fB[q]];
                pb1[q] = W[(size_t)(k0 + 2 * kpB[q] + 1) * D_FF + f0 + fB[q]];
            }
        }
        __syncthreads();
        mma_chunk(d, As_h[buf], Bs_h[buf], wm, wn, g, c);
    }

    // epilogue: bias + exact gelu -> packed fp16 H
#pragma unroll
    for (int mt = 0; mt < 4; mt++)
#pragma unroll
        for (int half = 0; half < 2; half++) {
            const int m = wm * 64 + mt * 16 + g + half * 8;
            if (m0 + m >= cnt) continue;
            const size_t hbase = (size_t)(roff + m0 + m) * HKP;
#pragma unroll
            for (int nt = 0; nt < 4; nt++) {
                const int f = f0 + wn * 32 + nt * 8 + 2 * c;
                float v0 = d[mt][nt][half * 2 + 0] + bias[f];
                float v1 = d[mt][nt][half * 2 + 1] + bias[f + 1];
                v0 = 0.5f * v0 * (1.0f + erff(v0 * 0.70710678118654752f));
                v1 = 0.5f * v1 * (1.0f + erff(v1 * 0.70710678118654752f));
                g_Hh[hbase + (f >> 1)] = pack2h(v0, v1);
            }
        }
}

// ----------------------------- FFN2: out += w*(H @ W2 + b2) ----------------
// grid (D_MODEL/128, 64, 9), 2-stage double buffer, A staged directly (fp16).
__global__ void __launch_bounds__(256)
k_ffn2(float* __restrict__ out,
       const float* __restrict__ w2,  const float* __restrict__ b2,
       const float* __restrict__ uw2, const float* __restrict__ ub2) {
    const int z    = blockIdx.z;
    const int roff = g_offset[z];
    const int cnt  = g_offset[z + 1] - roff;
    const int m0   = blockIdx.y * 128;
    if (m0 >= cnt) return;
    const int d0   = blockIdx.x * 128;

    const float* __restrict__ W    = (z < N_EXPERTS) ? (w2 + (size_t)z * D_FF * D_MODEL) : uw2;
    const float* __restrict__ bias = (z < N_EXPERTS) ? (b2 + (size_t)z * D_MODEL) : ub2;

    __shared__ int      s_tok[128];
    __shared__ float    s_w[128];
    __shared__ uint32_t As_h[2][AWORDS];
    __shared__ uint32_t Bs_h[2][BWORDS];

    const int tid  = threadIdx.x;
    const int wid  = tid >> 5;
    const int lane = tid & 31;
    const int wm = wid >> 2, wn = wid & 3;
    const int g = lane >> 2, c = lane & 3;

    if (tid < 128) {
        const int mm = m0 + tid;
        const int rr = roff + ((mm < cnt) ? mm : 0);
        s_tok[tid] = g_assign_tok[rr];
        s_w[tid]   = g_assign_w[rr];
    }
    __syncthreads();

    int   rA[4], kpA[4], kpB[4], fB[4];
    size_t arowp[4];
#pragma unroll
    for (int q = 0; q < 4; q++) {
        const int ia = tid + q * 256;
        rA[q]  = ia >> 3;  kpA[q] = ia & 7;
        const int mm = m0 + rA[q];
        arowp[q] = (size_t)(roff + ((mm < cnt) ? mm : m0)) * HKP;
        kpB[q] = ia >> 7;  fB[q]  = ia & 127;
    }

    float d[4][4][4];
#pragma unroll
    for (int a = 0; a < 4; a++)
#pragma unroll
        for (int b = 0; b < 4; b++)
#pragma unroll
            for (int e = 0; e < 4; e++) d[a][b][e] = 0.f;

    uint32_t pah[4];
    float    pb0[4], pb1[4];
#pragma unroll
    for (int q = 0; q < 4; q++) {
        pah[q] = g_Hh[arowp[q] + kpA[q]];
        pb0[q] = W[(size_t)(2 * kpB[q])     * D_MODEL + d0 + fB[q]];
        pb1[q] = W[(size_t)(2 * kpB[q] + 1) * D_MODEL + d0 + fB[q]];
    }

    constexpr int NCH = D_FF / 16;   // 128
    for (int ch = 0; ch < NCH; ch++) {
        const int buf = ch & 1;
#pragma unroll
        for (int q = 0; q < 4; q++) {
            As_h[buf][rA[q] * ASTRIDE + kpA[q]] = pah[q];
            Bs_h[buf][kpB[q] * BSTRIDE + fB[q]] = pack2h(pb0[q], pb1[q]);
        }
        if (ch + 1 < NCH) {
            const int kp0 = (ch + 1) * 8;
            const int k0  = (ch + 1) * 16;
#pragma unroll
            for (int q = 0; q < 4; q++) {
                pah[q] = g_Hh[arowp[q] + kp0 + kpA[q]];
                pb0[q] = W[(size_t)(k0 + 2 * kpB[q])     * D_MODEL + d0 + fB[q]];
                pb1[q] = W[(size_t)(k0 + 2 * kpB[q] + 1) * D_MODEL + d0 + fB[q]];
            }
        }
        __syncthreads();
        mma_chunk(d, As_h[buf], Bs_h[buf], wm, wn, g, c);
    }

    // epilogue: weighted atomic accumulation
#pragma unroll
    for (int mt = 0; mt < 4; mt++)
#pragma unroll
        for (int half = 0; half < 2; half++) {
            const int m = wm * 64 + mt * 16 + g + half * 8;
            if (m0 + m >= cnt) continue;
            const int   tok = s_tok[m];
            const float wr  = s_w[m];
            float* orow = out + (size_t)tok * D_MODEL;
#pragma unroll
            for (int nt = 0; nt < 4; nt++) {
                const int dd = d0 + wn * 32 + nt * 8 + 2 * c;
                atomicAdd(&orow[dd],     wr * (d[mt][nt][half * 2 + 0] + bias[dd]));
                atomicAdd(&orow[dd + 1], wr * (d[mt][nt][half * 2 + 1] + bias[dd + 1]));
            }
        }
}

// ----------------------------- launch --------------------------------------
extern "C" void kernel_launch(void* const* d_in, const int* in_sizes, int n_in,
                              void* d_out, int out_size) {
    const float* x        = (const float*)d_in[0];
    const int*   task_ids = (const int*)  d_in[1];
    const float* temb     = (const float*)d_in[2];
    const float* gw       = (const float*)d_in[3];
    const float* gb       = (const float*)d_in[4];
    const float* w1       = (const float*)d_in[5];
    const float* b1       = (const float*)d_in[6];
    const float* w2       = (const float*)d_in[7];
    const float* b2       = (const float*)d_in[8];
    const float* uw1      = (const float*)d_in[9];
    const float* ub1      = (const float*)d_in[10];
    const float* uw2      = (const float*)d_in[11];
    const float* ub2      = (const float*)d_in[12];

    float* out        = (float*)d_out;
    float* out_logits = out + OUT_ELEMS;

    k_zero<<<OUT_ELEMS / 4 / 256, 256>>>((float4*)out);
    k_gate<<<TOK, 256>>>(x, task_ids, temb, gw, gb, out_logits);
    k_scan<<<1, 32>>>();
    k_place<<<TOK / 256, 256>>>();
    k_ffn1<<<dim3(D_FF / 128, TOK / 128, NGRP), 256>>>(x, w1, b1, uw1, ub1);
    k_ffn2<<<dim3(D_MODEL / 128, TOK / 128, NGRP), 256>>>(out, w2, b2, uw2, ub2);
}